// round 1
// baseline (speedup 1.0000x reference)
#include <cuda_runtime.h>
#include <cstdint>

// Problem constants
#define B_  8
#define T_  1024
#define S_  1024
#define H_  1024
#define V_  5000
#define M_  (B_ * T_)   // 8192 rows

// Scratch (static device globals — allocation-free)
__device__ float g_h[(size_t)M_ * H_];   // gelu(x@Wf + bf), 32 MB
__device__ float g_pgen[M_];             // sigmoid(x@Wg + bg)

// ---------------------------------------------------------------------------
// Kernel 1: p_gen = sigmoid(x @ Wg + bg)   (one block per row)
// ---------------------------------------------------------------------------
__global__ void pgen_kernel(const float* __restrict__ x,
                            const float* __restrict__ Wg,
                            const float* __restrict__ bg,
                            float* __restrict__ pgen) {
    int r = blockIdx.x;
    const float* xr = x + (size_t)r * H_;
    float s = 0.f;
    for (int i = threadIdx.x; i < H_; i += blockDim.x)
        s += xr[i] * Wg[i];
    // block reduce (256 threads)
    __shared__ float red[8];
    #pragma unroll
    for (int o = 16; o; o >>= 1) s += __shfl_xor_sync(0xFFFFFFFFu, s, o);
    if ((threadIdx.x & 31) == 0) red[threadIdx.x >> 5] = s;
    __syncthreads();
    if (threadIdx.x < 8) {
        s = red[threadIdx.x];
        #pragma unroll
        for (int o = 4; o; o >>= 1) s += __shfl_xor_sync(0xFFu, s, o);
        if (threadIdx.x == 0) {
            float z = s + bg[0];
            pgen[r] = 1.f / (1.f + expf(-z));
        }
    }
}

// ---------------------------------------------------------------------------
// Tiled SGEMM: C[M,N] = epi(A[M,K] @ B[K,N] + bias[N])
// BM=BN=128, BK=16, 256 threads, 8x8 register tile per thread.
// EPI == 0 : tanh-approx GELU (matches jax.nn.gelu default approximate=True)
// EPI == 1 : identity
// M and K assumed multiples of tile sizes (true here: M=8192, K=1024).
// N may be ragged (V=5000).
// ---------------------------------------------------------------------------
#define BM 128
#define BN 128
#define BK 16
#define TM 8
#define TN 8

__device__ __forceinline__ float gelu_tanh(float v) {
    const float c = 0.7978845608028654f;   // sqrt(2/pi)
    float u = c * (v + 0.044715f * v * v * v);
    return 0.5f * v * (1.f + tanhf(u));
}

template <int EPI>
__global__ __launch_bounds__(256, 2)
void sgemm_kernel(const float* __restrict__ A,
                  const float* __restrict__ Bmat,
                  const float* __restrict__ bias,
                  float* __restrict__ C,
                  int N, int K) {
    __shared__ float As[BK][BM];
    __shared__ float Bs[BK][BN + 4];

    const int tid = threadIdx.x;
    const int rowBase = blockIdx.y * BM;
    const int colBase = blockIdx.x * BN;

    const int tr = (tid >> 4) * TM;   // thread row within tile (0..120)
    const int tc = (tid & 15) * TN;   // thread col within tile (0..120)

    float acc[TM][TN];
    #pragma unroll
    for (int i = 0; i < TM; i++)
        #pragma unroll
        for (int j = 0; j < TN; j++) acc[i][j] = 0.f;

    const bool fullN = (colBase + BN) <= N;

    for (int k0 = 0; k0 < K; k0 += BK) {
        // --- load A tile (128x16), store transposed As[k][m] ---
        #pragma unroll
        for (int l = 0; l < 2; l++) {
            int idx  = tid + l * 256;       // 0..511 float4 slots
            int arow = idx >> 2;            // 0..127
            int ac   = (idx & 3) * 4;       // 0,4,8,12
            float4 v = *(const float4*)&A[(size_t)(rowBase + arow) * K + k0 + ac];
            As[ac + 0][arow] = v.x;
            As[ac + 1][arow] = v.y;
            As[ac + 2][arow] = v.z;
            As[ac + 3][arow] = v.w;
        }
        // --- load B tile (16x128) ---
        #pragma unroll
        for (int l = 0; l < 2; l++) {
            int idx  = tid + l * 256;
            int brow = idx >> 5;            // 0..15
            int bc   = (idx & 31) * 4;      // 0..124
            int gcol = colBase + bc;
            float4 v;
            if (fullN) {
                v = *(const float4*)&Bmat[(size_t)(k0 + brow) * N + gcol];
            } else {
                const float* bp = &Bmat[(size_t)(k0 + brow) * N];
                v.x = (gcol + 0 < N) ? bp[gcol + 0] : 0.f;
                v.y = (gcol + 1 < N) ? bp[gcol + 1] : 0.f;
                v.z = (gcol + 2 < N) ? bp[gcol + 2] : 0.f;
                v.w = (gcol + 3 < N) ? bp[gcol + 3] : 0.f;
            }
            Bs[brow][bc + 0] = v.x;
            Bs[brow][bc + 1] = v.y;
            Bs[brow][bc + 2] = v.z;
            Bs[brow][bc + 3] = v.w;
        }
        __syncthreads();

        #pragma unroll
        for (int k = 0; k < BK; k++) {
            float a[TM], b[TN];
            #pragma unroll
            for (int i = 0; i < TM; i++) a[i] = As[k][tr + i];
            #pragma unroll
            for (int j = 0; j < TN; j++) b[j] = Bs[k][tc + j];
            #pragma unroll
            for (int i = 0; i < TM; i++)
                #pragma unroll
                for (int j = 0; j < TN; j++)
                    acc[i][j] = fmaf(a[i], b[j], acc[i][j]);
        }
        __syncthreads();
    }

    // --- epilogue: bias (+ gelu) ---
    #pragma unroll
    for (int i = 0; i < TM; i++) {
        int gr = rowBase + tr + i;
        float* crow = C + (size_t)gr * N;
        #pragma unroll
        for (int j = 0; j < TN; j++) {
            int gc = colBase + tc + j;
            if (gc < N) {
                float v = acc[i][j] + bias[gc];
                if (EPI == 0) v = gelu_tanh(v);
                crow[gc] = v;
            }
        }
    }
}

// ---------------------------------------------------------------------------
// Kernel 4: per-row softmax * p_gen + shared-memory scatter-add, write out.
// logits live in d_out (in-place safe: whole row cached in smem first).
// ---------------------------------------------------------------------------
__global__ __launch_bounds__(256)
void softmax_scatter_kernel(const float* __restrict__ attn,
                            const int*   __restrict__ nodes,
                            const float* __restrict__ pgen,
                            float* __restrict__ out) {
    __shared__ float srow[V_];
    __shared__ float red[9];

    const int r   = blockIdx.x;
    const int b   = r / T_;
    const int tid = threadIdx.x;
    float* orow   = out + (size_t)r * V_;

    // load logits, local max
    float mx = -3.0e38f;
    for (int i = tid; i < V_; i += 256) {
        float v = orow[i];
        srow[i] = v;
        mx = fmaxf(mx, v);
    }
    // block reduce max
    #pragma unroll
    for (int o = 16; o; o >>= 1) mx = fmaxf(mx, __shfl_xor_sync(0xFFFFFFFFu, mx, o));
    if ((tid & 31) == 0) red[tid >> 5] = mx;
    __syncthreads();
    if (tid < 8) {
        float v = red[tid];
        #pragma unroll
        for (int o = 4; o; o >>= 1) v = fmaxf(v, __shfl_xor_sync(0xFFu, v, o));
        if (tid == 0) red[8] = v;
    }
    __syncthreads();
    mx = red[8];

    // exp + local sum
    float sum = 0.f;
    for (int i = tid; i < V_; i += 256) {
        float e = __expf(srow[i] - mx);
        srow[i] = e;
        sum += e;
    }
    __syncthreads();   // protect red[] reuse
    #pragma unroll
    for (int o = 16; o; o >>= 1) sum += __shfl_xor_sync(0xFFFFFFFFu, sum, o);
    if ((tid & 31) == 0) red[tid >> 5] = sum;
    __syncthreads();
    if (tid < 8) {
        float v = red[tid];
        #pragma unroll
        for (int o = 4; o; o >>= 1) v += __shfl_xor_sync(0xFFu, v, o);
        if (tid == 0) red[8] = v;
    }
    __syncthreads();
    sum = red[8];

    const float pg    = pgen[r];
    const float scale = pg / sum;
    for (int i = tid; i < V_; i += 256) srow[i] *= scale;
    __syncthreads();

    // scatter-add pointer mass
    const float cpg = 1.f - pg;
    const float* ar = attn  + (size_t)r * S_;
    const int*   nb = nodes + (size_t)b * S_;
    for (int s = tid; s < S_; s += 256) {
        atomicAdd(&srow[nb[s]], ar[s] * cpg);
    }
    __syncthreads();

    // write back
    for (int i = tid; i < V_; i += 256) orow[i] = srow[i];
}

// ---------------------------------------------------------------------------
// Launch
// ---------------------------------------------------------------------------
extern "C" void kernel_launch(void* const* d_in, const int* in_sizes, int n_in,
                              void* d_out, int out_size) {
    const float* x    = (const float*)d_in[0];
    const float* attn = (const float*)d_in[1];
    const int*   nodes= (const int*)  d_in[2];
    const float* Wg   = (const float*)d_in[3];
    const float* bg   = (const float*)d_in[4];
    const float* Wf   = (const float*)d_in[5];
    const float* bf   = (const float*)d_in[6];
    const float* Wv   = (const float*)d_in[7];
    const float* bv   = (const float*)d_in[8];
    float* out        = (float*)d_out;

    float* h;    cudaGetSymbolAddress((void**)&h,    g_h);
    float* pgen; cudaGetSymbolAddress((void**)&pgen, g_pgen);

    // 1) p_gen
    pgen_kernel<<<M_, 256>>>(x, Wg, bg, pgen);

    // 2) h = gelu(x @ Wf + bf)
    {
        dim3 grid(H_ / BN, M_ / BM);   // (8, 64)
        sgemm_kernel<0><<<grid, 256>>>(x, Wf, bf, h, H_, H_);
    }

    // 3) logits = h @ Wv + bv  -> d_out
    {
        dim3 grid((V_ + BN - 1) / BN, M_ / BM);   // (40, 64)
        sgemm_kernel<1><<<grid, 256>>>(h, Wv, bv, out, V_, H_);
    }

    // 4) softmax * p_gen + scatter-add
    softmax_scatter_kernel<<<M_, 256>>>(attn, nodes, pgen, out);
}

// round 3
// speedup vs baseline: 2.9919x; 2.9919x over previous
#include <cuda_runtime.h>
#include <cstdint>

// Problem constants
#define B_  8
#define T_  1024
#define S_  1024
#define H_  1024
#define V_  5000
#define M_  (B_ * T_)   // 8192 rows
#define VPAD 5120       // V padded to multiple of 128

// Scratch (static device globals — allocation-free)
__device__ float g_h[(size_t)M_ * H_];        // gelu(x@Wf + bf), 32 MB
__device__ float g_pgen[M_];                  // sigmoid(x@Wg + bg)
__device__ float g_WfT[(size_t)H_ * H_];      // Wf^T  [N=H][K=H]
__device__ float g_WvT[(size_t)VPAD * H_];    // Wv^T  [N=VPAD][K=H], zero-padded

// ---------------------------------------------------------------------------
// helpers
// ---------------------------------------------------------------------------
__device__ __forceinline__ uint32_t smem_u32(const void* p) {
    return (uint32_t)__cvta_generic_to_shared(p);
}
__device__ __forceinline__ void cp_async16(uint32_t dst, const void* src) {
    asm volatile("cp.async.cg.shared.global [%0], [%1], 16;" :: "r"(dst), "l"(src));
}
__device__ __forceinline__ void cp_commit() {
    asm volatile("cp.async.commit_group;" ::: "memory");
}
template <int N>
__device__ __forceinline__ void cp_wait() {
    asm volatile("cp.async.wait_group %0;" :: "n"(N) : "memory");
}

// m16n8k8 tf32 mma (sm_80+ portable)
__device__ __forceinline__ void mma_tf32(float& d0, float& d1, float& d2, float& d3,
                                         uint32_t a0, uint32_t a1, uint32_t a2, uint32_t a3,
                                         uint32_t b0, uint32_t b1) {
    asm volatile(
        "mma.sync.aligned.m16n8k8.row.col.f32.tf32.tf32.f32 "
        "{%0,%1,%2,%3}, {%4,%5,%6,%7}, {%8,%9}, {%0,%1,%2,%3};"
        : "+f"(d0), "+f"(d1), "+f"(d2), "+f"(d3)
        : "r"(a0), "r"(a1), "r"(a2), "r"(a3), "r"(b0), "r"(b1));
}

__device__ __forceinline__ float gelu_tanh(float v) {
    const float c = 0.7978845608028654f;   // sqrt(2/pi)
    float u = c * (v + 0.044715f * v * v * v);
    return 0.5f * v * (1.f + tanhf(u));
}

// ---------------------------------------------------------------------------
// Kernel: 32x32 tiled transpose with zero-pad.  Wt[c][r] = (c<C) ? W[r][c] : 0
// ---------------------------------------------------------------------------
__global__ void transpose_kernel(const float* __restrict__ W, float* __restrict__ Wt,
                                 int R, int C, int Cpad) {
    __shared__ float t[32][33];
    int c0 = blockIdx.x * 32;
    int r0 = blockIdx.y * 32;
    #pragma unroll
    for (int k = 0; k < 4; k++) {
        int r = r0 + threadIdx.y + k * 8;
        int c = c0 + threadIdx.x;
        float v = 0.f;
        if (r < R && c < C) v = W[(size_t)r * C + c];
        t[threadIdx.y + k * 8][threadIdx.x] = v;
    }
    __syncthreads();
    #pragma unroll
    for (int k = 0; k < 4; k++) {
        int rr = c0 + threadIdx.y + k * 8;
        int cc = r0 + threadIdx.x;
        if (rr < Cpad && cc < R)
            Wt[(size_t)rr * R + cc] = t[threadIdx.x][threadIdx.y + k * 8];
    }
}

// ---------------------------------------------------------------------------
// Kernel: p_gen = sigmoid(x @ Wg + bg)
// ---------------------------------------------------------------------------
__global__ void pgen_kernel(const float* __restrict__ x,
                            const float* __restrict__ Wg,
                            const float* __restrict__ bg,
                            float* __restrict__ pgen) {
    int r = blockIdx.x;
    const float* xr = x + (size_t)r * H_;
    float s = 0.f;
    for (int i = threadIdx.x; i < H_; i += blockDim.x)
        s += xr[i] * Wg[i];
    __shared__ float red[8];
    #pragma unroll
    for (int o = 16; o; o >>= 1) s += __shfl_xor_sync(0xFFFFFFFFu, s, o);
    if ((threadIdx.x & 31) == 0) red[threadIdx.x >> 5] = s;
    __syncthreads();
    if (threadIdx.x < 8) {
        s = red[threadIdx.x];
        #pragma unroll
        for (int o = 4; o; o >>= 1) s += __shfl_xor_sync(0xFFu, s, o);
        if (threadIdx.x == 0) {
            float z = s + bg[0];
            pgen[r] = 1.f / (1.f + expf(-z));
        }
    }
}

// ---------------------------------------------------------------------------
// tf32 mma.sync GEMM: C[M,N] = epi(A[M,K] @ Bt[N,K]^T + bias[N])
// BM=BN=128, BK=32, 256 threads (8 warps, 2x4), warp tile 64x32.
// SMEM [row][BK+4] padded layout -> conflict-free fragment gathers.
// Double-buffered cp.async.  EPI 0: tanh-GELU, 1: identity.
// ---------------------------------------------------------------------------
#define BM 128
#define BN 128
#define BK 32
#define KP (BK + 4)                         // padded row length (floats)
#define STAGE_FLOATS (BM * KP)              // per operand per stage = 4608
#define DYNSMEM (2 * 2 * STAGE_FLOATS * 4)  // 73728 bytes

template <int EPI>
__global__ __launch_bounds__(256, 2)
void mma_gemm_kernel(const float* __restrict__ A, const float* __restrict__ Bt,
                     const float* __restrict__ bias, float* __restrict__ C,
                     int Nreal, int K) {
    extern __shared__ float sm[];
    // layout: As0 | Bs0 | As1 | Bs1
    float* As[2] = { sm,                    sm + 2 * STAGE_FLOATS };
    float* Bs[2] = { sm + STAGE_FLOATS,     sm + 3 * STAGE_FLOATS };

    const int tid  = threadIdx.x;
    const int wid  = tid >> 5;
    const int lane = tid & 31;
    const int g    = lane >> 2;   // 0..7
    const int t    = lane & 3;    // 0..3
    const int wm   = (wid >> 2) * 64;   // warp M offset: 0 or 64
    const int wn   = (wid & 3) * 32;    // warp N offset: 0,32,64,96

    const int rowBase = blockIdx.y * BM;
    const int colBase = blockIdx.x * BN;
    const int NK = K / BK;

    const float* Abase = A  + (size_t)rowBase * K;
    const float* Bbase = Bt + (size_t)colBase * K;

    float acc[4][4][4];
    #pragma unroll
    for (int i = 0; i < 4; i++)
        #pragma unroll
        for (int j = 0; j < 4; j++)
            #pragma unroll
            for (int r = 0; r < 4; r++) acc[i][j][r] = 0.f;

    // stage loader: 128 rows x 32 floats each for A and B (16B chunks)
    auto load_stage = [&](int st, int k0) {
        uint32_t aDst = smem_u32(As[st]);
        uint32_t bDst = smem_u32(Bs[st]);
        #pragma unroll
        for (int i = 0; i < 4; i++) {
            int idx = tid + i * 256;        // 0..1023
            int r   = idx >> 3;             // 0..127
            int kq  = (idx & 7) * 4;        // 0,4,...,28
            uint32_t off = (uint32_t)(r * KP + kq) * 4u;
            cp_async16(aDst + off, Abase + (size_t)r * K + k0 + kq);
            cp_async16(bDst + off, Bbase + (size_t)r * K + k0 + kq);
        }
        cp_commit();
    };

    load_stage(0, 0);

    for (int it = 0; it < NK; it++) {
        if (it + 1 < NK) { load_stage((it + 1) & 1, (it + 1) * BK); cp_wait<1>(); }
        else             { cp_wait<0>(); }
        __syncthreads();

        const float* as = As[it & 1];
        const float* bs = Bs[it & 1];

        #pragma unroll
        for (int kk = 0; kk < 4; kk++) {
            const int k8 = kk * 8;
            uint32_t a[4][4];
            #pragma unroll
            for (int mt = 0; mt < 4; mt++) {
                int m0 = wm + mt * 16 + g;
                a[mt][0] = __float_as_uint(as[(m0    ) * KP + k8 + t    ]);
                a[mt][1] = __float_as_uint(as[(m0 + 8) * KP + k8 + t    ]);
                a[mt][2] = __float_as_uint(as[(m0    ) * KP + k8 + t + 4]);
                a[mt][3] = __float_as_uint(as[(m0 + 8) * KP + k8 + t + 4]);
            }
            uint32_t b[4][2];
            #pragma unroll
            for (int nt = 0; nt < 4; nt++) {
                int n0 = wn + nt * 8 + g;
                b[nt][0] = __float_as_uint(bs[n0 * KP + k8 + t    ]);
                b[nt][1] = __float_as_uint(bs[n0 * KP + k8 + t + 4]);
            }
            #pragma unroll
            for (int mt = 0; mt < 4; mt++)
                #pragma unroll
                for (int nt = 0; nt < 4; nt++)
                    mma_tf32(acc[mt][nt][0], acc[mt][nt][1],
                             acc[mt][nt][2], acc[mt][nt][3],
                             a[mt][0], a[mt][1], a[mt][2], a[mt][3],
                             b[nt][0], b[nt][1]);
        }
        __syncthreads();
    }

    // epilogue: c0,c1 at (row0, col0/col0+1); c2,c3 at (row0+8, ...)
    #pragma unroll
    for (int mt = 0; mt < 4; mt++) {
        int row0 = rowBase + wm + mt * 16 + g;
        float* crow0 = C + (size_t)row0 * Nreal;
        float* crow1 = C + (size_t)(row0 + 8) * Nreal;
        #pragma unroll
        for (int nt = 0; nt < 4; nt++) {
            int col0 = colBase + wn + nt * 8 + 2 * t;
            if (col0 + 1 < Nreal) {
                float b0 = bias[col0], b1 = bias[col0 + 1];
                float v0 = acc[mt][nt][0] + b0;
                float v1 = acc[mt][nt][1] + b1;
                float v2 = acc[mt][nt][2] + b0;
                float v3 = acc[mt][nt][3] + b1;
                if (EPI == 0) {
                    v0 = gelu_tanh(v0); v1 = gelu_tanh(v1);
                    v2 = gelu_tanh(v2); v3 = gelu_tanh(v3);
                }
                float2 p0 = make_float2(v0, v1);
                float2 p1 = make_float2(v2, v3);
                *(float2*)&crow0[col0] = p0;
                *(float2*)&crow1[col0] = p1;
            } else if (col0 < Nreal) {
                float b0 = bias[col0];
                float v0 = acc[mt][nt][0] + b0;
                float v2 = acc[mt][nt][2] + b0;
                if (EPI == 0) { v0 = gelu_tanh(v0); v2 = gelu_tanh(v2); }
                crow0[col0] = v0;
                crow1[col0] = v2;
            }
        }
    }
}

// ---------------------------------------------------------------------------
// Kernel: per-row softmax * p_gen + shared-memory scatter-add, write out.
// ---------------------------------------------------------------------------
__global__ __launch_bounds__(256)
void softmax_scatter_kernel(const float* __restrict__ attn,
                            const int*   __restrict__ nodes,
                            const float* __restrict__ pgen,
                            float* __restrict__ out) {
    __shared__ float srow[V_];
    __shared__ float red[9];

    const int r   = blockIdx.x;
    const int b   = r / T_;
    const int tid = threadIdx.x;
    float* orow   = out + (size_t)r * V_;

    float mx = -3.0e38f;
    for (int i = tid; i < V_; i += 256) {
        float v = orow[i];
        srow[i] = v;
        mx = fmaxf(mx, v);
    }
    #pragma unroll
    for (int o = 16; o; o >>= 1) mx = fmaxf(mx, __shfl_xor_sync(0xFFFFFFFFu, mx, o));
    if ((tid & 31) == 0) red[tid >> 5] = mx;
    __syncthreads();
    if (tid < 8) {
        float v = red[tid];
        #pragma unroll
        for (int o = 4; o; o >>= 1) v = fmaxf(v, __shfl_xor_sync(0xFFu, v, o));
        if (tid == 0) red[8] = v;
    }
    __syncthreads();
    mx = red[8];

    float sum = 0.f;
    for (int i = tid; i < V_; i += 256) {
        float e = __expf(srow[i] - mx);
        srow[i] = e;
        sum += e;
    }
    __syncthreads();
    #pragma unroll
    for (int o = 16; o; o >>= 1) sum += __shfl_xor_sync(0xFFFFFFFFu, sum, o);
    if ((tid & 31) == 0) red[tid >> 5] = sum;
    __syncthreads();
    if (tid < 8) {
        float v = red[tid];
        #pragma unroll
        for (int o = 4; o; o >>= 1) v += __shfl_xor_sync(0xFFu, v, o);
        if (tid == 0) red[8] = v;
    }
    __syncthreads();
    sum = red[8];

    const float pg    = pgen[r];
    const float scale = pg / sum;
    for (int i = tid; i < V_; i += 256) srow[i] *= scale;
    __syncthreads();

    const float cpg = 1.f - pg;
    const float* ar = attn  + (size_t)r * S_;
    const int*   nb = nodes + (size_t)b * S_;
    for (int s = tid; s < S_; s += 256) {
        atomicAdd(&srow[nb[s]], ar[s] * cpg);
    }
    __syncthreads();

    for (int i = tid; i < V_; i += 256) orow[i] = srow[i];
}

// ---------------------------------------------------------------------------
// Launch
// ---------------------------------------------------------------------------
extern "C" void kernel_launch(void* const* d_in, const int* in_sizes, int n_in,
                              void* d_out, int out_size) {
    const float* x    = (const float*)d_in[0];
    const float* attn = (const float*)d_in[1];
    const int*   nodes= (const int*)  d_in[2];
    const float* Wg   = (const float*)d_in[3];
    const float* bg   = (const float*)d_in[4];
    const float* Wf   = (const float*)d_in[5];
    const float* bf   = (const float*)d_in[6];
    const float* Wv   = (const float*)d_in[7];
    const float* bv   = (const float*)d_in[8];
    float* out        = (float*)d_out;

    float* h;    cudaGetSymbolAddress((void**)&h,    g_h);
    float* pgen; cudaGetSymbolAddress((void**)&pgen, g_pgen);
    float* WfT;  cudaGetSymbolAddress((void**)&WfT,  g_WfT);
    float* WvT;  cudaGetSymbolAddress((void**)&WvT,  g_WvT);

    cudaFuncSetAttribute(mma_gemm_kernel<0>, cudaFuncAttributeMaxDynamicSharedMemorySize, DYNSMEM);
    cudaFuncSetAttribute(mma_gemm_kernel<1>, cudaFuncAttributeMaxDynamicSharedMemorySize, DYNSMEM);

    // Weight transposes (K-major B operands); WvT zero-padded to 5120 rows
    transpose_kernel<<<dim3(H_ / 32, H_ / 32), dim3(32, 8)>>>(Wf, WfT, H_, H_, H_);
    transpose_kernel<<<dim3(VPAD / 32, H_ / 32), dim3(32, 8)>>>(Wv, WvT, H_, V_, VPAD);

    // p_gen
    pgen_kernel<<<M_, 256>>>(x, Wg, bg, pgen);

    // h = gelu(x @ Wf + bf)
    mma_gemm_kernel<0><<<dim3(H_ / BN, M_ / BM), 256, DYNSMEM>>>(x, WfT, bf, h, H_, H_);

    // logits = h @ Wv + bv  -> d_out
    mma_gemm_kernel<1><<<dim3(VPAD / BN, M_ / BM), 256, DYNSMEM>>>(h, WvT, bv, out, V_, H_);

    // softmax * p_gen + pointer scatter
    softmax_scatter_kernel<<<M_, 256>>>(attn, nodes, pgen, out);
}

// round 4
// speedup vs baseline: 4.1936x; 1.4017x over previous
#include <cuda_runtime.h>
#include <cuda_bf16.h>
#include <cstdint>

// Problem constants
#define B_  8
#define T_  1024
#define S_  1024
#define H_  1024
#define V_  5000
#define M_  (B_ * T_)   // 8192 rows
#define VPAD 5120       // V padded to multiple of 128

// Scratch (static device globals — allocation-free)
__device__ __nv_bfloat16 g_hb[(size_t)M_ * H_];    // gelu(x@Wf+bf) in bf16, 16 MB
__device__ float g_pgen[M_];                       // sigmoid(x@Wg + bg)
__device__ float g_WfT[(size_t)H_ * H_];           // Wf^T  [N=H][K=H] fp32
__device__ __nv_bfloat16 g_WvTb[(size_t)VPAD * H_];// Wv^T  [N=VPAD][K=H] bf16, padded

// ---------------------------------------------------------------------------
// helpers
// ---------------------------------------------------------------------------
__device__ __forceinline__ uint32_t smem_u32(const void* p) {
    return (uint32_t)__cvta_generic_to_shared(p);
}
__device__ __forceinline__ void cp_async16(uint32_t dst, const void* src) {
    asm volatile("cp.async.cg.shared.global [%0], [%1], 16;" :: "r"(dst), "l"(src));
}
__device__ __forceinline__ void cp_commit() {
    asm volatile("cp.async.commit_group;" ::: "memory");
}
template <int N>
__device__ __forceinline__ void cp_wait() {
    asm volatile("cp.async.wait_group %0;" :: "n"(N) : "memory");
}

// m16n8k8 tf32 mma (sm_80+)
__device__ __forceinline__ void mma_tf32(float& d0, float& d1, float& d2, float& d3,
                                         uint32_t a0, uint32_t a1, uint32_t a2, uint32_t a3,
                                         uint32_t b0, uint32_t b1) {
    asm volatile(
        "mma.sync.aligned.m16n8k8.row.col.f32.tf32.tf32.f32 "
        "{%0,%1,%2,%3}, {%4,%5,%6,%7}, {%8,%9}, {%0,%1,%2,%3};"
        : "+f"(d0), "+f"(d1), "+f"(d2), "+f"(d3)
        : "r"(a0), "r"(a1), "r"(a2), "r"(a3), "r"(b0), "r"(b1));
}

// m16n8k16 bf16 mma (sm_80+)
__device__ __forceinline__ void mma_bf16(float& d0, float& d1, float& d2, float& d3,
                                         uint32_t a0, uint32_t a1, uint32_t a2, uint32_t a3,
                                         uint32_t b0, uint32_t b1) {
    asm volatile(
        "mma.sync.aligned.m16n8k16.row.col.f32.bf16.bf16.f32 "
        "{%0,%1,%2,%3}, {%4,%5,%6,%7}, {%8,%9}, {%0,%1,%2,%3};"
        : "+f"(d0), "+f"(d1), "+f"(d2), "+f"(d3)
        : "r"(a0), "r"(a1), "r"(a2), "r"(a3), "r"(b0), "r"(b1));
}

__device__ __forceinline__ void ldsm_x4(uint32_t& r0, uint32_t& r1, uint32_t& r2, uint32_t& r3,
                                        uint32_t addr) {
    asm volatile("ldmatrix.sync.aligned.m8n8.x4.shared.b16 {%0,%1,%2,%3}, [%4];"
                 : "=r"(r0), "=r"(r1), "=r"(r2), "=r"(r3) : "r"(addr));
}

__device__ __forceinline__ float gelu_tanh(float v) {
    const float c = 0.7978845608028654f;   // sqrt(2/pi)
    float u = c * (v + 0.044715f * v * v * v);
    return 0.5f * v * (1.f + tanhf(u));
}

// ---------------------------------------------------------------------------
// Transposes (fp32 out and bf16 out), 32x32 tiles, zero-pad rows beyond C.
// ---------------------------------------------------------------------------
__global__ void transpose_kernel(const float* __restrict__ W, float* __restrict__ Wt,
                                 int R, int C, int Cpad) {
    __shared__ float t[32][33];
    int c0 = blockIdx.x * 32;
    int r0 = blockIdx.y * 32;
    #pragma unroll
    for (int k = 0; k < 4; k++) {
        int r = r0 + threadIdx.y + k * 8;
        int c = c0 + threadIdx.x;
        float v = 0.f;
        if (r < R && c < C) v = W[(size_t)r * C + c];
        t[threadIdx.y + k * 8][threadIdx.x] = v;
    }
    __syncthreads();
    #pragma unroll
    for (int k = 0; k < 4; k++) {
        int rr = c0 + threadIdx.y + k * 8;
        int cc = r0 + threadIdx.x;
        if (rr < Cpad && cc < R)
            Wt[(size_t)rr * R + cc] = t[threadIdx.x][threadIdx.y + k * 8];
    }
}

__global__ void transpose_bf16_kernel(const float* __restrict__ W, __nv_bfloat16* __restrict__ Wt,
                                      int R, int C, int Cpad) {
    __shared__ float t[32][33];
    int c0 = blockIdx.x * 32;
    int r0 = blockIdx.y * 32;
    #pragma unroll
    for (int k = 0; k < 4; k++) {
        int r = r0 + threadIdx.y + k * 8;
        int c = c0 + threadIdx.x;
        float v = 0.f;
        if (r < R && c < C) v = W[(size_t)r * C + c];
        t[threadIdx.y + k * 8][threadIdx.x] = v;
    }
    __syncthreads();
    #pragma unroll
    for (int k = 0; k < 4; k++) {
        int rr = c0 + threadIdx.y + k * 8;
        int cc = r0 + threadIdx.x;
        if (rr < Cpad && cc < R)
            Wt[(size_t)rr * R + cc] = __float2bfloat16_rn(t[threadIdx.x][threadIdx.y + k * 8]);
    }
}

// ---------------------------------------------------------------------------
// p_gen = sigmoid(x @ Wg + bg)
// ---------------------------------------------------------------------------
__global__ void pgen_kernel(const float* __restrict__ x,
                            const float* __restrict__ Wg,
                            const float* __restrict__ bg,
                            float* __restrict__ pgen) {
    int r = blockIdx.x;
    const float* xr = x + (size_t)r * H_;
    float s = 0.f;
    for (int i = threadIdx.x; i < H_; i += blockDim.x)
        s += xr[i] * Wg[i];
    __shared__ float red[8];
    #pragma unroll
    for (int o = 16; o; o >>= 1) s += __shfl_xor_sync(0xFFFFFFFFu, s, o);
    if ((threadIdx.x & 31) == 0) red[threadIdx.x >> 5] = s;
    __syncthreads();
    if (threadIdx.x < 8) {
        s = red[threadIdx.x];
        #pragma unroll
        for (int o = 4; o; o >>= 1) s += __shfl_xor_sync(0xFFu, s, o);
        if (threadIdx.x == 0) {
            float z = s + bg[0];
            pgen[r] = 1.f / (1.f + expf(-z));
        }
    }
}

// ---------------------------------------------------------------------------
// tf32 mma.sync GEMM (GEMM1): h_bf16 = gelu(x @ WfT^T + bf)
// BM=BN=128, BK=32, 256 threads (8 warps, 2x4), warp tile 64x32.
// ---------------------------------------------------------------------------
#define BM 128
#define BN 128
#define BK 32
#define KP (BK + 4)
#define STAGE_FLOATS (BM * KP)
#define DYNSMEM1 (2 * 2 * STAGE_FLOATS * 4)   // 73728 bytes

__global__ __launch_bounds__(256, 2)
void tf32_gemm_gelu_kernel(const float* __restrict__ A, const float* __restrict__ Bt,
                           const float* __restrict__ bias, __nv_bfloat16* __restrict__ C,
                           int N, int K) {
    extern __shared__ float sm[];
    float* As[2] = { sm,                sm + 2 * STAGE_FLOATS };
    float* Bs[2] = { sm + STAGE_FLOATS, sm + 3 * STAGE_FLOATS };

    const int tid  = threadIdx.x;
    const int wid  = tid >> 5;
    const int lane = tid & 31;
    const int g    = lane >> 2;
    const int t    = lane & 3;
    const int wm   = (wid >> 2) * 64;
    const int wn   = (wid & 3) * 32;

    const int rowBase = blockIdx.y * BM;
    const int colBase = blockIdx.x * BN;
    const int NK = K / BK;

    const float* Abase = A  + (size_t)rowBase * K;
    const float* Bbase = Bt + (size_t)colBase * K;

    float acc[4][4][4];
    #pragma unroll
    for (int i = 0; i < 4; i++)
        #pragma unroll
        for (int j = 0; j < 4; j++)
            #pragma unroll
            for (int r = 0; r < 4; r++) acc[i][j][r] = 0.f;

    auto load_stage = [&](int st, int k0) {
        uint32_t aDst = smem_u32(As[st]);
        uint32_t bDst = smem_u32(Bs[st]);
        #pragma unroll
        for (int i = 0; i < 4; i++) {
            int idx = tid + i * 256;
            int r   = idx >> 3;
            int kq  = (idx & 7) * 4;
            uint32_t off = (uint32_t)(r * KP + kq) * 4u;
            cp_async16(aDst + off, Abase + (size_t)r * K + k0 + kq);
            cp_async16(bDst + off, Bbase + (size_t)r * K + k0 + kq);
        }
        cp_commit();
    };

    load_stage(0, 0);

    for (int it = 0; it < NK; it++) {
        if (it + 1 < NK) { load_stage((it + 1) & 1, (it + 1) * BK); cp_wait<1>(); }
        else             { cp_wait<0>(); }
        __syncthreads();

        const float* as = As[it & 1];
        const float* bs = Bs[it & 1];

        #pragma unroll
        for (int kk = 0; kk < 4; kk++) {
            const int k8 = kk * 8;
            uint32_t a[4][4];
            #pragma unroll
            for (int mt = 0; mt < 4; mt++) {
                int m0 = wm + mt * 16 + g;
                a[mt][0] = __float_as_uint(as[(m0    ) * KP + k8 + t    ]);
                a[mt][1] = __float_as_uint(as[(m0 + 8) * KP + k8 + t    ]);
                a[mt][2] = __float_as_uint(as[(m0    ) * KP + k8 + t + 4]);
                a[mt][3] = __float_as_uint(as[(m0 + 8) * KP + k8 + t + 4]);
            }
            uint32_t b[4][2];
            #pragma unroll
            for (int nt = 0; nt < 4; nt++) {
                int n0 = wn + nt * 8 + g;
                b[nt][0] = __float_as_uint(bs[n0 * KP + k8 + t    ]);
                b[nt][1] = __float_as_uint(bs[n0 * KP + k8 + t + 4]);
            }
            #pragma unroll
            for (int mt = 0; mt < 4; mt++)
                #pragma unroll
                for (int nt = 0; nt < 4; nt++)
                    mma_tf32(acc[mt][nt][0], acc[mt][nt][1],
                             acc[mt][nt][2], acc[mt][nt][3],
                             a[mt][0], a[mt][1], a[mt][2], a[mt][3],
                             b[nt][0], b[nt][1]);
        }
        __syncthreads();
    }

    // epilogue: bias + gelu -> bf16
    #pragma unroll
    for (int mt = 0; mt < 4; mt++) {
        int row0 = rowBase + wm + mt * 16 + g;
        __nv_bfloat16* crow0 = C + (size_t)row0 * N;
        __nv_bfloat16* crow1 = C + (size_t)(row0 + 8) * N;
        #pragma unroll
        for (int nt = 0; nt < 4; nt++) {
            int col0 = colBase + wn + nt * 8 + 2 * t;
            float b0 = bias[col0], b1 = bias[col0 + 1];
            float v0 = gelu_tanh(acc[mt][nt][0] + b0);
            float v1 = gelu_tanh(acc[mt][nt][1] + b1);
            float v2 = gelu_tanh(acc[mt][nt][2] + b0);
            float v3 = gelu_tanh(acc[mt][nt][3] + b1);
            __nv_bfloat162 p0, p1;
            p0.x = __float2bfloat16_rn(v0); p0.y = __float2bfloat16_rn(v1);
            p1.x = __float2bfloat16_rn(v2); p1.y = __float2bfloat16_rn(v3);
            *(__nv_bfloat162*)&crow0[col0] = p0;
            *(__nv_bfloat162*)&crow1[col0] = p1;
        }
    }
}

// ---------------------------------------------------------------------------
// bf16 mma.sync GEMM (GEMM2): logits = h_bf @ WvT^T + bv  (fp32 out)
// BM=BN=128, BK=32 bf16, 256 threads, warp tile 64x32, ldmatrix.x4 operands.
// SMEM rows padded to 40 bf16 (80 B) -> conflict-free LDSM.
// ---------------------------------------------------------------------------
#define KP2 40
#define STAGE2_BYTES (128 * KP2 * 2)          // 10240 B per operand per stage
#define DYNSMEM2 (4 * STAGE2_BYTES)           // 40960 B

__global__ __launch_bounds__(256, 2)
void bf16_gemm_kernel(const __nv_bfloat16* __restrict__ A,
                      const __nv_bfloat16* __restrict__ Bt,
                      const float* __restrict__ bias, float* __restrict__ C,
                      int Nreal, int K) {
    extern __shared__ char sm2[];
    // layout: As0 | Bs0 | As1 | Bs1
    uint32_t base = smem_u32(sm2);
    uint32_t AsO[2] = { base,                    base + 2 * STAGE2_BYTES };
    uint32_t BsO[2] = { base + STAGE2_BYTES,     base + 3 * STAGE2_BYTES };

    const int tid  = threadIdx.x;
    const int wid  = tid >> 5;
    const int lane = tid & 31;
    const int g    = lane >> 2;
    const int t    = lane & 3;
    const int wm   = (wid >> 2) * 64;
    const int wn   = (wid & 3) * 32;

    const int rowBase = blockIdx.y * BM;
    const int colBase = blockIdx.x * BN;
    const int NK = K / BK;   // BK=32 bf16 per stage

    const __nv_bfloat16* Abase = A  + (size_t)rowBase * K;
    const __nv_bfloat16* Bbase = Bt + (size_t)colBase * K;

    float acc[4][4][4];
    #pragma unroll
    for (int i = 0; i < 4; i++)
        #pragma unroll
        for (int j = 0; j < 4; j++)
            #pragma unroll
            for (int r = 0; r < 4; r++) acc[i][j][r] = 0.f;

    // per-stage loader: 128 rows x 32 bf16 (64 B) per operand = 512 16B chunks
    auto load_stage = [&](int st, int k0) {
        #pragma unroll
        for (int i = 0; i < 2; i++) {
            int idx = tid + i * 256;        // 0..511
            int r   = idx >> 2;             // 0..127
            int c   = idx & 3;              // 16B chunk
            uint32_t off = (uint32_t)(r * (KP2 * 2) + c * 16);
            cp_async16(AsO[st] + off, Abase + (size_t)r * K + k0 + c * 8);
            cp_async16(BsO[st] + off, Bbase + (size_t)r * K + k0 + c * 8);
        }
        cp_commit();
    };

    // ldmatrix per-thread address components
    const uint32_t aRowOff = (uint32_t)(lane & 15) * (KP2 * 2);
    const uint32_t aKh     = (uint32_t)(lane >> 4) * 16;
    const uint32_t bRowOff = (uint32_t)((lane & 7) + ((lane >> 4) << 3)) * (KP2 * 2);
    const uint32_t bKh     = (uint32_t)((lane >> 3) & 1) * 16;

    load_stage(0, 0);

    for (int it = 0; it < NK; it++) {
        if (it + 1 < NK) { load_stage((it + 1) & 1, (it + 1) * BK); cp_wait<1>(); }
        else             { cp_wait<0>(); }
        __syncthreads();

        uint32_t as = AsO[it & 1];
        uint32_t bs = BsO[it & 1];

        #pragma unroll
        for (int kk = 0; kk < 2; kk++) {        // two k16 steps
            uint32_t kb = kk * 32;              // 16 bf16 = 32 B
            uint32_t afr[4][4];
            #pragma unroll
            for (int mt = 0; mt < 4; mt++) {
                ldsm_x4(afr[mt][0], afr[mt][1], afr[mt][2], afr[mt][3],
                        as + (uint32_t)(wm + mt * 16) * (KP2 * 2) + aRowOff + kb + aKh);
            }
            uint32_t bfr[4][2];
            #pragma unroll
            for (int p = 0; p < 2; p++) {
                uint32_t r0, r1, r2, r3;
                ldsm_x4(r0, r1, r2, r3,
                        bs + (uint32_t)(wn + p * 16) * (KP2 * 2) + bRowOff + kb + bKh);
                bfr[2 * p][0]     = r0; bfr[2 * p][1]     = r1;
                bfr[2 * p + 1][0] = r2; bfr[2 * p + 1][1] = r3;
            }
            #pragma unroll
            for (int mt = 0; mt < 4; mt++)
                #pragma unroll
                for (int nt = 0; nt < 4; nt++)
                    mma_bf16(acc[mt][nt][0], acc[mt][nt][1],
                             acc[mt][nt][2], acc[mt][nt][3],
                             afr[mt][0], afr[mt][1], afr[mt][2], afr[mt][3],
                             bfr[nt][0], bfr[nt][1]);
        }
        __syncthreads();
    }

    // epilogue: bias, fp32 out with N bounds (V=5000 ragged)
    #pragma unroll
    for (int mt = 0; mt < 4; mt++) {
        int row0 = rowBase + wm + mt * 16 + g;
        float* crow0 = C + (size_t)row0 * Nreal;
        float* crow1 = C + (size_t)(row0 + 8) * Nreal;
        #pragma unroll
        for (int nt = 0; nt < 4; nt++) {
            int col0 = colBase + wn + nt * 8 + 2 * t;
            if (col0 + 1 < Nreal) {
                float b0 = bias[col0], b1 = bias[col0 + 1];
                float2 p0 = make_float2(acc[mt][nt][0] + b0, acc[mt][nt][1] + b1);
                float2 p1 = make_float2(acc[mt][nt][2] + b0, acc[mt][nt][3] + b1);
                *(float2*)&crow0[col0] = p0;
                *(float2*)&crow1[col0] = p1;
            } else if (col0 < Nreal) {
                float b0 = bias[col0];
                crow0[col0] = acc[mt][nt][0] + b0;
                crow1[col0] = acc[mt][nt][2] + b0;
            }
        }
    }
}

// ---------------------------------------------------------------------------
// per-row softmax * p_gen + shared-memory scatter-add, write out.
// ---------------------------------------------------------------------------
__global__ __launch_bounds__(256)
void softmax_scatter_kernel(const float* __restrict__ attn,
                            const int*   __restrict__ nodes,
                            const float* __restrict__ pgen,
                            float* __restrict__ out) {
    __shared__ float srow[V_];
    __shared__ float red[9];

    const int r   = blockIdx.x;
    const int b   = r / T_;
    const int tid = threadIdx.x;
    float* orow   = out + (size_t)r * V_;

    float mx = -3.0e38f;
    for (int i = tid; i < V_; i += 256) {
        float v = orow[i];
        srow[i] = v;
        mx = fmaxf(mx, v);
    }
    #pragma unroll
    for (int o = 16; o; o >>= 1) mx = fmaxf(mx, __shfl_xor_sync(0xFFFFFFFFu, mx, o));
    if ((tid & 31) == 0) red[tid >> 5] = mx;
    __syncthreads();
    if (tid < 8) {
        float v = red[tid];
        #pragma unroll
        for (int o = 4; o; o >>= 1) v = fmaxf(v, __shfl_xor_sync(0xFFu, v, o));
        if (tid == 0) red[8] = v;
    }
    __syncthreads();
    mx = red[8];

    float sum = 0.f;
    for (int i = tid; i < V_; i += 256) {
        float e = __expf(srow[i] - mx);
        srow[i] = e;
        sum += e;
    }
    __syncthreads();
    #pragma unroll
    for (int o = 16; o; o >>= 1) sum += __shfl_xor_sync(0xFFFFFFFFu, sum, o);
    if ((tid & 31) == 0) red[tid >> 5] = sum;
    __syncthreads();
    if (tid < 8) {
        float v = red[tid];
        #pragma unroll
        for (int o = 4; o; o >>= 1) v += __shfl_xor_sync(0xFFu, v, o);
        if (tid == 0) red[8] = v;
    }
    __syncthreads();
    sum = red[8];

    const float pg    = pgen[r];
    const float scale = pg / sum;
    for (int i = tid; i < V_; i += 256) srow[i] *= scale;
    __syncthreads();

    const float cpg = 1.f - pg;
    const float* ar = attn  + (size_t)r * S_;
    const int*   nb = nodes + (size_t)b * S_;
    for (int s = tid; s < S_; s += 256) {
        atomicAdd(&srow[nb[s]], ar[s] * cpg);
    }
    __syncthreads();

    for (int i = tid; i < V_; i += 256) orow[i] = srow[i];
}

// ---------------------------------------------------------------------------
// Launch
// ---------------------------------------------------------------------------
extern "C" void kernel_launch(void* const* d_in, const int* in_sizes, int n_in,
                              void* d_out, int out_size) {
    const float* x    = (const float*)d_in[0];
    const float* attn = (const float*)d_in[1];
    const int*   nodes= (const int*)  d_in[2];
    const float* Wg   = (const float*)d_in[3];
    const float* bg   = (const float*)d_in[4];
    const float* Wf   = (const float*)d_in[5];
    const float* bf   = (const float*)d_in[6];
    const float* Wv   = (const float*)d_in[7];
    const float* bv   = (const float*)d_in[8];
    float* out        = (float*)d_out;

    __nv_bfloat16* hb;   cudaGetSymbolAddress((void**)&hb,   g_hb);
    float* pgen;         cudaGetSymbolAddress((void**)&pgen, g_pgen);
    float* WfT;          cudaGetSymbolAddress((void**)&WfT,  g_WfT);
    __nv_bfloat16* WvTb; cudaGetSymbolAddress((void**)&WvTb, g_WvTb);

    cudaFuncSetAttribute(tf32_gemm_gelu_kernel, cudaFuncAttributeMaxDynamicSharedMemorySize, DYNSMEM1);
    cudaFuncSetAttribute(bf16_gemm_kernel,      cudaFuncAttributeMaxDynamicSharedMemorySize, DYNSMEM2);

    // Weight transposes (K-major B operands)
    transpose_kernel<<<dim3(H_ / 32, H_ / 32), dim3(32, 8)>>>(Wf, WfT, H_, H_, H_);
    transpose_bf16_kernel<<<dim3(VPAD / 32, H_ / 32), dim3(32, 8)>>>(Wv, WvTb, H_, V_, VPAD);

    // p_gen
    pgen_kernel<<<M_, 256>>>(x, Wg, bg, pgen);

    // h_bf16 = gelu(x @ Wf + bf)
    tf32_gemm_gelu_kernel<<<dim3(H_ / BN, M_ / BM), 256, DYNSMEM1>>>(x, WfT, bf, hb, H_, H_);

    // logits = h_bf @ Wv + bv -> d_out
    bf16_gemm_kernel<<<dim3(VPAD / BN, M_ / BM), 256, DYNSMEM2>>>(hb, WvTb, bv, out, V_, H_);

    // softmax * p_gen + pointer scatter
    softmax_scatter_kernel<<<M_, 256>>>(attn, nodes, pgen, out);
}

// round 5
// speedup vs baseline: 5.0089x; 1.1944x over previous
#include <cuda_runtime.h>
#include <cuda_bf16.h>
#include <cstdint>

// Problem constants
#define B_  8
#define T_  1024
#define S_  1024
#define H_  1024
#define V_  5000
#define M_  (B_ * T_)   // 8192 rows
#define VPAD 5120       // V padded to multiple of 128

// Scratch (static device globals — allocation-free)
__device__ __nv_bfloat16 g_xb[(size_t)M_ * H_];    // x in bf16, 16 MB
__device__ __nv_bfloat16 g_hb[(size_t)M_ * H_];    // gelu(x@Wf+bf) in bf16, 16 MB
__device__ float g_pgen[M_];                       // sigmoid(x@Wg + bg)
__device__ __nv_bfloat16 g_WfTb[(size_t)H_ * H_];  // Wf^T bf16 [N=H][K=H]
__device__ __nv_bfloat16 g_WvTb[(size_t)VPAD * H_];// Wv^T bf16 [N=VPAD][K=H], padded

// ---------------------------------------------------------------------------
// helpers
// ---------------------------------------------------------------------------
__device__ __forceinline__ uint32_t smem_u32(const void* p) {
    return (uint32_t)__cvta_generic_to_shared(p);
}
__device__ __forceinline__ void cp_async16(uint32_t dst, const void* src) {
    asm volatile("cp.async.cg.shared.global [%0], [%1], 16;" :: "r"(dst), "l"(src));
}
__device__ __forceinline__ void cp_commit() {
    asm volatile("cp.async.commit_group;" ::: "memory");
}
template <int N>
__device__ __forceinline__ void cp_wait() {
    asm volatile("cp.async.wait_group %0;" :: "n"(N) : "memory");
}

// m16n8k16 bf16 mma (sm_80+)
__device__ __forceinline__ void mma_bf16(float& d0, float& d1, float& d2, float& d3,
                                         uint32_t a0, uint32_t a1, uint32_t a2, uint32_t a3,
                                         uint32_t b0, uint32_t b1) {
    asm volatile(
        "mma.sync.aligned.m16n8k16.row.col.f32.bf16.bf16.f32 "
        "{%0,%1,%2,%3}, {%4,%5,%6,%7}, {%8,%9}, {%0,%1,%2,%3};"
        : "+f"(d0), "+f"(d1), "+f"(d2), "+f"(d3)
        : "r"(a0), "r"(a1), "r"(a2), "r"(a3), "r"(b0), "r"(b1));
}

__device__ __forceinline__ void ldsm_x4(uint32_t& r0, uint32_t& r1, uint32_t& r2, uint32_t& r3,
                                        uint32_t addr) {
    asm volatile("ldmatrix.sync.aligned.m8n8.x4.shared.b16 {%0,%1,%2,%3}, [%4];"
                 : "=r"(r0), "=r"(r1), "=r"(r2), "=r"(r3) : "r"(addr));
}

__device__ __forceinline__ float gelu_tanh(float v) {
    const float c = 0.7978845608028654f;   // sqrt(2/pi)
    float u = c * (v + 0.044715f * v * v * v);
    return 0.5f * v * (1.f + tanhf(u));
}

// ---------------------------------------------------------------------------
// x (fp32) -> bf16 copy
// ---------------------------------------------------------------------------
__global__ void cvt_bf16_kernel(const float* __restrict__ in,
                                __nv_bfloat16* __restrict__ out, int n4) {
    int i = blockIdx.x * blockDim.x + threadIdx.x;
    if (i < n4) {
        float4 v = ((const float4*)in)[i];
        __nv_bfloat162 p0, p1;
        p0.x = __float2bfloat16_rn(v.x); p0.y = __float2bfloat16_rn(v.y);
        p1.x = __float2bfloat16_rn(v.z); p1.y = __float2bfloat16_rn(v.w);
        ((__nv_bfloat162*)out)[2 * i]     = p0;
        ((__nv_bfloat162*)out)[2 * i + 1] = p1;
    }
}

// ---------------------------------------------------------------------------
// Transpose fp32 -> bf16, 32x32 tiles, zero-pad rows beyond C.
// ---------------------------------------------------------------------------
__global__ void transpose_bf16_kernel(const float* __restrict__ W, __nv_bfloat16* __restrict__ Wt,
                                      int R, int C, int Cpad) {
    __shared__ float t[32][33];
    int c0 = blockIdx.x * 32;
    int r0 = blockIdx.y * 32;
    #pragma unroll
    for (int k = 0; k < 4; k++) {
        int r = r0 + threadIdx.y + k * 8;
        int c = c0 + threadIdx.x;
        float v = 0.f;
        if (r < R && c < C) v = W[(size_t)r * C + c];
        t[threadIdx.y + k * 8][threadIdx.x] = v;
    }
    __syncthreads();
    #pragma unroll
    for (int k = 0; k < 4; k++) {
        int rr = c0 + threadIdx.y + k * 8;
        int cc = r0 + threadIdx.x;
        if (rr < Cpad && cc < R)
            Wt[(size_t)rr * R + cc] = __float2bfloat16_rn(t[threadIdx.x][threadIdx.y + k * 8]);
    }
}

// ---------------------------------------------------------------------------
// p_gen = sigmoid(x @ Wg + bg)   (fp32 x, full precision)
// ---------------------------------------------------------------------------
__global__ void pgen_kernel(const float* __restrict__ x,
                            const float* __restrict__ Wg,
                            const float* __restrict__ bg,
                            float* __restrict__ pgen) {
    int r = blockIdx.x;
    const float* xr = x + (size_t)r * H_;
    float s = 0.f;
    for (int i = threadIdx.x; i < H_; i += blockDim.x)
        s += xr[i] * Wg[i];
    __shared__ float red[8];
    #pragma unroll
    for (int o = 16; o; o >>= 1) s += __shfl_xor_sync(0xFFFFFFFFu, s, o);
    if ((threadIdx.x & 31) == 0) red[threadIdx.x >> 5] = s;
    __syncthreads();
    if (threadIdx.x < 8) {
        s = red[threadIdx.x];
        #pragma unroll
        for (int o = 4; o; o >>= 1) s += __shfl_xor_sync(0xFFu, s, o);
        if (threadIdx.x == 0) {
            float z = s + bg[0];
            pgen[r] = 1.f / (1.f + expf(-z));
        }
    }
}

// ---------------------------------------------------------------------------
// Unified bf16 mma.sync GEMM: C = epi(A[M,K] @ Bt[N,K]^T + bias[N])
// BM=BN=128, BK=32 bf16, 256 threads (8 warps 2x4), warp tile 64x32.
// 3-stage cp.async pipeline. SMEM rows padded to 40 bf16 -> conflict-free LDSM.
// EPI 0: gelu -> bf16 out.  EPI 1: identity -> fp32 out (ragged N).
// ---------------------------------------------------------------------------
#define BM 128
#define BN 128
#define BK 32
#define KP2 40
#define STAGE2_BYTES (128 * KP2 * 2)          // 10240 B per operand per stage
#define NSTAGE 3
#define DYNSMEM2 (NSTAGE * 2 * STAGE2_BYTES)  // 61440 B

template <int EPI, typename OutT>
__global__ __launch_bounds__(256, 2)
void bf16_gemm_kernel(const __nv_bfloat16* __restrict__ A,
                      const __nv_bfloat16* __restrict__ Bt,
                      const float* __restrict__ bias, OutT* __restrict__ C,
                      int Nreal, int K) {
    extern __shared__ char sm2[];
    uint32_t base = smem_u32(sm2);
    // layout: [A0 B0][A1 B1][A2 B2]
    uint32_t AsO[NSTAGE], BsO[NSTAGE];
    #pragma unroll
    for (int s = 0; s < NSTAGE; s++) {
        AsO[s] = base + (uint32_t)s * 2 * STAGE2_BYTES;
        BsO[s] = AsO[s] + STAGE2_BYTES;
    }

    const int tid  = threadIdx.x;
    const int wid  = tid >> 5;
    const int lane = tid & 31;
    const int g    = lane >> 2;
    const int t    = lane & 3;
    const int wm   = (wid >> 2) * 64;
    const int wn   = (wid & 3) * 32;

    const int rowBase = blockIdx.y * BM;
    const int colBase = blockIdx.x * BN;
    const int NK = K / BK;

    const __nv_bfloat16* Abase = A  + (size_t)rowBase * K;
    const __nv_bfloat16* Bbase = Bt + (size_t)colBase * K;

    float acc[4][4][4];
    #pragma unroll
    for (int i = 0; i < 4; i++)
        #pragma unroll
        for (int j = 0; j < 4; j++)
            #pragma unroll
            for (int r = 0; r < 4; r++) acc[i][j][r] = 0.f;

    auto load_stage = [&](int st, int k0) {
        #pragma unroll
        for (int i = 0; i < 2; i++) {
            int idx = tid + i * 256;        // 0..511
            int r   = idx >> 2;             // 0..127
            int c   = idx & 3;              // 16B chunk
            uint32_t off = (uint32_t)(r * (KP2 * 2) + c * 16);
            cp_async16(AsO[st] + off, Abase + (size_t)r * K + k0 + c * 8);
            cp_async16(BsO[st] + off, Bbase + (size_t)r * K + k0 + c * 8);
        }
        cp_commit();
    };

    // ldmatrix per-thread address components
    const uint32_t aRowOff = (uint32_t)(lane & 15) * (KP2 * 2);
    const uint32_t aKh     = (uint32_t)(lane >> 4) * 16;
    const uint32_t bRowOff = (uint32_t)((lane & 7) + ((lane >> 4) << 3)) * (KP2 * 2);
    const uint32_t bKh     = (uint32_t)((lane >> 3) & 1) * 16;

    // prologue: stages 0,1
    load_stage(0, 0);
    load_stage(1, BK);

    for (int it = 0; it < NK; it++) {
        int st = it % NSTAGE;
        // prefetch stage it+2 (its buffer freed by end-sync of iter it-1)
        if (it + 2 < NK) { load_stage((it + 2) % NSTAGE, (it + 2) * BK); cp_wait<2>(); }
        else if (it + 1 < NK) { cp_wait<1>(); }
        else { cp_wait<0>(); }
        __syncthreads();

        uint32_t as = AsO[st];
        uint32_t bs = BsO[st];

        #pragma unroll
        for (int kk = 0; kk < 2; kk++) {        // two k16 steps
            uint32_t kb = kk * 32;              // 16 bf16 = 32 B
            uint32_t afr[4][4];
            #pragma unroll
            for (int mt = 0; mt < 4; mt++) {
                ldsm_x4(afr[mt][0], afr[mt][1], afr[mt][2], afr[mt][3],
                        as + (uint32_t)(wm + mt * 16) * (KP2 * 2) + aRowOff + kb + aKh);
            }
            uint32_t bfr[4][2];
            #pragma unroll
            for (int p = 0; p < 2; p++) {
                uint32_t r0, r1, r2, r3;
                ldsm_x4(r0, r1, r2, r3,
                        bs + (uint32_t)(wn + p * 16) * (KP2 * 2) + bRowOff + kb + bKh);
                bfr[2 * p][0]     = r0; bfr[2 * p][1]     = r1;
                bfr[2 * p + 1][0] = r2; bfr[2 * p + 1][1] = r3;
            }
            #pragma unroll
            for (int mt = 0; mt < 4; mt++)
                #pragma unroll
                for (int nt = 0; nt < 4; nt++)
                    mma_bf16(acc[mt][nt][0], acc[mt][nt][1],
                             acc[mt][nt][2], acc[mt][nt][3],
                             afr[mt][0], afr[mt][1], afr[mt][2], afr[mt][3],
                             bfr[nt][0], bfr[nt][1]);
        }
        __syncthreads();
    }

    // epilogue
    #pragma unroll
    for (int mt = 0; mt < 4; mt++) {
        int row0 = rowBase + wm + mt * 16 + g;
        OutT* crow0 = C + (size_t)row0 * Nreal;
        OutT* crow1 = C + (size_t)(row0 + 8) * Nreal;
        #pragma unroll
        for (int nt = 0; nt < 4; nt++) {
            int col0 = colBase + wn + nt * 8 + 2 * t;
            if constexpr (EPI == 0) {
                // gelu -> bf16, N always full (H=1024)
                float b0 = bias[col0], b1 = bias[col0 + 1];
                float v0 = gelu_tanh(acc[mt][nt][0] + b0);
                float v1 = gelu_tanh(acc[mt][nt][1] + b1);
                float v2 = gelu_tanh(acc[mt][nt][2] + b0);
                float v3 = gelu_tanh(acc[mt][nt][3] + b1);
                __nv_bfloat162 p0, p1;
                p0.x = __float2bfloat16_rn(v0); p0.y = __float2bfloat16_rn(v1);
                p1.x = __float2bfloat16_rn(v2); p1.y = __float2bfloat16_rn(v3);
                *(__nv_bfloat162*)&crow0[col0] = p0;
                *(__nv_bfloat162*)&crow1[col0] = p1;
            } else {
                if (col0 + 1 < Nreal) {
                    float b0 = bias[col0], b1 = bias[col0 + 1];
                    float2 p0 = make_float2(acc[mt][nt][0] + b0, acc[mt][nt][1] + b1);
                    float2 p1 = make_float2(acc[mt][nt][2] + b0, acc[mt][nt][3] + b1);
                    *(float2*)&crow0[col0] = p0;
                    *(float2*)&crow1[col0] = p1;
                } else if (col0 < Nreal) {
                    float b0 = bias[col0];
                    crow0[col0] = acc[mt][nt][0] + b0;
                    crow1[col0] = acc[mt][nt][2] + b0;
                }
            }
        }
    }
}

// ---------------------------------------------------------------------------
// per-row softmax * p_gen + shared-memory scatter-add, write out.
// 512 threads, float4 I/O (V=5000 -> 1250 float4, S=1024 -> 256 float4).
// ---------------------------------------------------------------------------
#define SMT 512
__global__ __launch_bounds__(SMT)
void softmax_scatter_kernel(const float* __restrict__ attn,
                            const int*   __restrict__ nodes,
                            const float* __restrict__ pgen,
                            float* __restrict__ out) {
    __shared__ float srow[V_];
    __shared__ float red[17];

    const int r   = blockIdx.x;
    const int b   = r / T_;
    const int tid = threadIdx.x;
    float* orow   = out + (size_t)r * V_;
    const int nwarp = SMT / 32;

    // load logits (float4), local max
    float mx = -3.0e38f;
    for (int i = tid; i < V_ / 4; i += SMT) {
        float4 v = ((const float4*)orow)[i];
        ((float4*)srow)[i] = v;
        mx = fmaxf(fmaxf(mx, fmaxf(v.x, v.y)), fmaxf(v.z, v.w));
    }
    #pragma unroll
    for (int o = 16; o; o >>= 1) mx = fmaxf(mx, __shfl_xor_sync(0xFFFFFFFFu, mx, o));
    if ((tid & 31) == 0) red[tid >> 5] = mx;
    __syncthreads();
    if (tid < nwarp) {
        float v = red[tid];
        #pragma unroll
        for (int o = 8; o; o >>= 1) v = fmaxf(v, __shfl_xor_sync(0xFFFFu, v, o));
        if (tid == 0) red[16] = v;
    }
    __syncthreads();
    mx = red[16];

    // exp + local sum
    float sum = 0.f;
    for (int i = tid; i < V_ / 4; i += SMT) {
        float4 v = ((float4*)srow)[i];
        v.x = __expf(v.x - mx); v.y = __expf(v.y - mx);
        v.z = __expf(v.z - mx); v.w = __expf(v.w - mx);
        ((float4*)srow)[i] = v;
        sum += v.x + v.y + v.z + v.w;
    }
    __syncthreads();
    #pragma unroll
    for (int o = 16; o; o >>= 1) sum += __shfl_xor_sync(0xFFFFFFFFu, sum, o);
    if ((tid & 31) == 0) red[tid >> 5] = sum;
    __syncthreads();
    if (tid < nwarp) {
        float v = red[tid];
        #pragma unroll
        for (int o = 8; o; o >>= 1) v += __shfl_xor_sync(0xFFFFu, v, o);
        if (tid == 0) red[16] = v;
    }
    __syncthreads();
    sum = red[16];

    const float pg    = pgen[r];
    const float scale = pg / sum;
    for (int i = tid; i < V_ / 4; i += SMT) {
        float4 v = ((float4*)srow)[i];
        v.x *= scale; v.y *= scale; v.z *= scale; v.w *= scale;
        ((float4*)srow)[i] = v;
    }
    __syncthreads();

    // scatter-add pointer mass (smem atomics)
    const float cpg = 1.f - pg;
    const float* ar = attn  + (size_t)r * S_;
    const int*   nb = nodes + (size_t)b * S_;
    for (int i = tid; i < S_ / 4; i += SMT) {
        float4 av = ((const float4*)ar)[i];
        int4   nv = ((const int4*)nb)[i];
        atomicAdd(&srow[nv.x], av.x * cpg);
        atomicAdd(&srow[nv.y], av.y * cpg);
        atomicAdd(&srow[nv.z], av.z * cpg);
        atomicAdd(&srow[nv.w], av.w * cpg);
    }
    __syncthreads();

    // write back (float4)
    for (int i = tid; i < V_ / 4; i += SMT)
        ((float4*)orow)[i] = ((const float4*)srow)[i];
}

// ---------------------------------------------------------------------------
// Launch
// ---------------------------------------------------------------------------
extern "C" void kernel_launch(void* const* d_in, const int* in_sizes, int n_in,
                              void* d_out, int out_size) {
    const float* x    = (const float*)d_in[0];
    const float* attn = (const float*)d_in[1];
    const int*   nodes= (const int*)  d_in[2];
    const float* Wg   = (const float*)d_in[3];
    const float* bg   = (const float*)d_in[4];
    const float* Wf   = (const float*)d_in[5];
    const float* bf   = (const float*)d_in[6];
    const float* Wv   = (const float*)d_in[7];
    const float* bv   = (const float*)d_in[8];
    float* out        = (float*)d_out;

    __nv_bfloat16* xb;   cudaGetSymbolAddress((void**)&xb,   g_xb);
    __nv_bfloat16* hb;   cudaGetSymbolAddress((void**)&hb,   g_hb);
    float* pgen;         cudaGetSymbolAddress((void**)&pgen, g_pgen);
    __nv_bfloat16* WfTb; cudaGetSymbolAddress((void**)&WfTb, g_WfTb);
    __nv_bfloat16* WvTb; cudaGetSymbolAddress((void**)&WvTb, g_WvTb);

    cudaFuncSetAttribute((const void*)bf16_gemm_kernel<0, __nv_bfloat16>,
                         cudaFuncAttributeMaxDynamicSharedMemorySize, DYNSMEM2);
    cudaFuncSetAttribute((const void*)bf16_gemm_kernel<1, float>,
                         cudaFuncAttributeMaxDynamicSharedMemorySize, DYNSMEM2);

    // prep: x -> bf16, weight transposes (bf16, K-major)
    cvt_bf16_kernel<<<(M_ * H_ / 4 + 255) / 256, 256>>>(x, xb, M_ * H_ / 4);
    transpose_bf16_kernel<<<dim3(H_ / 32, H_ / 32), dim3(32, 8)>>>(Wf, WfTb, H_, H_, H_);
    transpose_bf16_kernel<<<dim3(VPAD / 32, H_ / 32), dim3(32, 8)>>>(Wv, WvTb, H_, V_, VPAD);

    // p_gen (fp32)
    pgen_kernel<<<M_, 256>>>(x, Wg, bg, pgen);

    // h_bf16 = gelu(x @ Wf + bf)
    bf16_gemm_kernel<0, __nv_bfloat16><<<dim3(H_ / BN, M_ / BM), 256, DYNSMEM2>>>(
        xb, WfTb, bf, hb, H_, H_);

    // logits = h_bf @ Wv + bv -> d_out
    bf16_gemm_kernel<1, float><<<dim3(VPAD / BN, M_ / BM), 256, DYNSMEM2>>>(
        hb, WvTb, bv, out, V_, H_);

    // softmax * p_gen + pointer scatter
    softmax_scatter_kernel<<<M_, SMT>>>(attn, nodes, pgen, out);
}

// round 9
// speedup vs baseline: 5.1159x; 1.0214x over previous
#include <cuda_runtime.h>
#include <cuda_bf16.h>
#include <cstdint>

// Problem constants
#define B_  8
#define T_  1024
#define S_  1024
#define H_  1024
#define V_  5000
#define M_  (B_ * T_)   // 8192 rows
#define VPAD 5120       // V padded to multiple of 128

// Scratch (static device globals — allocation-free)
__device__ __nv_bfloat16 g_xb[(size_t)M_ * H_];    // x in bf16, 16 MB
__device__ __nv_bfloat16 g_hb[(size_t)M_ * H_];    // gelu(x@Wf+bf) in bf16, 16 MB
__device__ float g_pgen[M_];                       // sigmoid(x@Wg + bg)
__device__ __nv_bfloat16 g_WfTb[(size_t)H_ * H_];  // Wf^T bf16 [N=H][K=H]
__device__ __nv_bfloat16 g_WvTb[(size_t)VPAD * H_];// Wv^T bf16 [N=VPAD][K=H], padded

// ---------------------------------------------------------------------------
// helpers
// ---------------------------------------------------------------------------
__device__ __forceinline__ uint32_t smem_u32(const void* p) {
    return (uint32_t)__cvta_generic_to_shared(p);
}
__device__ __forceinline__ void cp_async16(uint32_t dst, const void* src) {
    asm volatile("cp.async.cg.shared.global [%0], [%1], 16;" :: "r"(dst), "l"(src));
}
__device__ __forceinline__ void cp_commit() {
    asm volatile("cp.async.commit_group;" ::: "memory");
}
template <int N>
__device__ __forceinline__ void cp_wait() {
    asm volatile("cp.async.wait_group %0;" :: "n"(N) : "memory");
}

// m16n8k16 bf16 mma (sm_80+)
__device__ __forceinline__ void mma_bf16(float& d0, float& d1, float& d2, float& d3,
                                         uint32_t a0, uint32_t a1, uint32_t a2, uint32_t a3,
                                         uint32_t b0, uint32_t b1) {
    asm volatile(
        "mma.sync.aligned.m16n8k16.row.col.f32.bf16.bf16.f32 "
        "{%0,%1,%2,%3}, {%4,%5,%6,%7}, {%8,%9}, {%0,%1,%2,%3};"
        : "+f"(d0), "+f"(d1), "+f"(d2), "+f"(d3)
        : "r"(a0), "r"(a1), "r"(a2), "r"(a3), "r"(b0), "r"(b1));
}

__device__ __forceinline__ void ldsm_x4(uint32_t& r0, uint32_t& r1, uint32_t& r2, uint32_t& r3,
                                        uint32_t addr) {
    asm volatile("ldmatrix.sync.aligned.m8n8.x4.shared.b16 {%0,%1,%2,%3}, [%4];"
                 : "=r"(r0), "=r"(r1), "=r"(r2), "=r"(r3) : "r"(addr));
}

__device__ __forceinline__ float gelu_tanh(float v) {
    const float c = 0.7978845608028654f;   // sqrt(2/pi)
    float u = c * (v + 0.044715f * v * v * v);
    return 0.5f * v * (1.f + tanhf(u));
}

// ---------------------------------------------------------------------------
// Transpose fp32 -> bf16, 32x32 tiles, zero-pad rows beyond C.
// ---------------------------------------------------------------------------
__global__ void transpose_bf16_kernel(const float* __restrict__ W, __nv_bfloat16* __restrict__ Wt,
                                      int R, int C, int Cpad) {
    __shared__ float t[32][33];
    int c0 = blockIdx.x * 32;
    int r0 = blockIdx.y * 32;
    #pragma unroll
    for (int k = 0; k < 4; k++) {
        int r = r0 + threadIdx.y + k * 8;
        int c = c0 + threadIdx.x;
        float v = 0.f;
        if (r < R && c < C) v = W[(size_t)r * C + c];
        t[threadIdx.y + k * 8][threadIdx.x] = v;
    }
    __syncthreads();
    #pragma unroll
    for (int k = 0; k < 4; k++) {
        int rr = c0 + threadIdx.y + k * 8;
        int cc = r0 + threadIdx.x;
        if (rr < Cpad && cc < R)
            Wt[(size_t)rr * R + cc] = __float2bfloat16_rn(t[threadIdx.x][threadIdx.y + k * 8]);
    }
}

// ---------------------------------------------------------------------------
// Fused: p_gen = sigmoid(x @ Wg + bg)  AND  xb = bf16(x)
// One block per row, 256 threads, float4 I/O.
// ---------------------------------------------------------------------------
__global__ __launch_bounds__(256)
void pgen_cvt_kernel(const float* __restrict__ x,
                     const float* __restrict__ Wg,
                     const float* __restrict__ bg,
                     float* __restrict__ pgen,
                     __nv_bfloat16* __restrict__ xb) {
    int r = blockIdx.x;
    const float* xr = x + (size_t)r * H_;
    __nv_bfloat16* xbr = xb + (size_t)r * H_;

    float s = 0.f;
    for (int i = threadIdx.x; i < H_ / 4; i += 256) {
        float4 v = ((const float4*)xr)[i];
        float4 w = ((const float4*)Wg)[i];
        s += v.x * w.x + v.y * w.y + v.z * w.z + v.w * w.w;
        __nv_bfloat162 p0, p1;
        p0.x = __float2bfloat16_rn(v.x); p0.y = __float2bfloat16_rn(v.y);
        p1.x = __float2bfloat16_rn(v.z); p1.y = __float2bfloat16_rn(v.w);
        ((__nv_bfloat162*)xbr)[2 * i]     = p0;
        ((__nv_bfloat162*)xbr)[2 * i + 1] = p1;
    }
    __shared__ float red[8];
    #pragma unroll
    for (int o = 16; o; o >>= 1) s += __shfl_xor_sync(0xFFFFFFFFu, s, o);
    if ((threadIdx.x & 31) == 0) red[threadIdx.x >> 5] = s;
    __syncthreads();
    if (threadIdx.x < 8) {
        s = red[threadIdx.x];
        #pragma unroll
        for (int o = 4; o; o >>= 1) s += __shfl_xor_sync(0xFFu, s, o);
        if (threadIdx.x == 0) {
            float z = s + bg[0];
            pgen[r] = 1.f / (1.f + expf(-z));
        }
    }
}

// ---------------------------------------------------------------------------
// Unified bf16 mma.sync GEMM: C = epi(A[M,K] @ Bt[N,K]^T + bias[N])
// BM=BN=128, BK=32 bf16, 256 threads (8 warps 2x4), warp tile 64x32.
// 4-stage cp.async pipeline, ONE __syncthreads per iteration.
// Full per-stage fragment prefetch (12 LDSM then 32 MMA).
// SMEM rows padded to 40 bf16 -> conflict-free LDSM.
// EPI 0: gelu -> bf16 out.  EPI 1: identity -> fp32 out (ragged N).
// ---------------------------------------------------------------------------
#define BM 128
#define BN 128
#define BK 32
#define KP2 40
#define STAGE2_BYTES (128 * KP2 * 2)          // 10240 B per operand per stage
#define NSTAGE 4
#define DYNSMEM2 (NSTAGE * 2 * STAGE2_BYTES)  // 81920 B

template <int EPI, typename OutT>
__global__ __launch_bounds__(256, 2)
void bf16_gemm_kernel(const __nv_bfloat16* __restrict__ A,
                      const __nv_bfloat16* __restrict__ Bt,
                      const float* __restrict__ bias, OutT* __restrict__ C,
                      int Nreal, int K) {
    extern __shared__ char sm2[];
    uint32_t base = smem_u32(sm2);
    uint32_t AsO[NSTAGE], BsO[NSTAGE];
    #pragma unroll
    for (int s = 0; s < NSTAGE; s++) {
        AsO[s] = base + (uint32_t)s * 2 * STAGE2_BYTES;
        BsO[s] = AsO[s] + STAGE2_BYTES;
    }

    const int tid  = threadIdx.x;
    const int wid  = tid >> 5;
    const int lane = tid & 31;
    const int g    = lane >> 2;
    const int t    = lane & 3;
    const int wm   = (wid >> 2) * 64;
    const int wn   = (wid & 3) * 32;

    const int rowBase = blockIdx.y * BM;
    const int colBase = blockIdx.x * BN;
    const int NK = K / BK;

    const __nv_bfloat16* Abase = A  + (size_t)rowBase * K;
    const __nv_bfloat16* Bbase = Bt + (size_t)colBase * K;

    float acc[4][4][4];
    #pragma unroll
    for (int i = 0; i < 4; i++)
        #pragma unroll
        for (int j = 0; j < 4; j++)
            #pragma unroll
            for (int r = 0; r < 4; r++) acc[i][j][r] = 0.f;

    auto load_stage = [&](int st, int k0) {
        #pragma unroll
        for (int i = 0; i < 2; i++) {
            int idx = tid + i * 256;        // 0..511
            int r   = idx >> 2;             // 0..127
            int c   = idx & 3;              // 16B chunk
            uint32_t off = (uint32_t)(r * (KP2 * 2) + c * 16);
            cp_async16(AsO[st] + off, Abase + (size_t)r * K + k0 + c * 8);
            cp_async16(BsO[st] + off, Bbase + (size_t)r * K + k0 + c * 8);
        }
        cp_commit();
    };

    // ldmatrix per-thread address components
    const uint32_t aRowOff = (uint32_t)(lane & 15) * (KP2 * 2);
    const uint32_t aKh     = (uint32_t)(lane >> 4) * 16;
    const uint32_t bRowOff = (uint32_t)((lane & 7) + ((lane >> 4) << 3)) * (KP2 * 2);
    const uint32_t bKh     = (uint32_t)((lane >> 3) & 1) * 16;

    // prologue: stages 0,1,2  (3 groups in flight)
    load_stage(0, 0);
    load_stage(1, BK);
    load_stage(2, 2 * BK);

    for (int it = 0; it < NK; it++) {
        int st = it % NSTAGE;
        // ensure stage it complete; keep later groups in flight
        if (it + 2 < NK)      { cp_wait<2>(); }
        else if (it + 1 < NK) { cp_wait<1>(); }
        else                  { cp_wait<0>(); }
        __syncthreads();   // data ready AND all warps done with stage it-1's buffer

        // prefetch stage it+3 into buffer (it+3)%4 == (it-1)%4 (freed by the sync)
        if (it + 3 < NK) load_stage((it + 3) % NSTAGE, (it + 3) * BK);

        uint32_t as = AsO[st];
        uint32_t bs = BsO[st];

        // -- load ALL fragments for this stage (both k16 steps): 12 LDSM --
        uint32_t afr[2][4][4];
        uint32_t bfr[2][4][2];
        #pragma unroll
        for (int kk = 0; kk < 2; kk++) {
            uint32_t kb = kk * 32;
            #pragma unroll
            for (int mt = 0; mt < 4; mt++)
                ldsm_x4(afr[kk][mt][0], afr[kk][mt][1], afr[kk][mt][2], afr[kk][mt][3],
                        as + (uint32_t)(wm + mt * 16) * (KP2 * 2) + aRowOff + kb + aKh);
            #pragma unroll
            for (int p = 0; p < 2; p++) {
                uint32_t r0, r1, r2, r3;
                ldsm_x4(r0, r1, r2, r3,
                        bs + (uint32_t)(wn + p * 16) * (KP2 * 2) + bRowOff + kb + bKh);
                bfr[kk][2 * p][0]     = r0; bfr[kk][2 * p][1]     = r1;
                bfr[kk][2 * p + 1][0] = r2; bfr[kk][2 * p + 1][1] = r3;
            }
        }
        // -- 32 MMAs --
        #pragma unroll
        for (int kk = 0; kk < 2; kk++)
            #pragma unroll
            for (int mt = 0; mt < 4; mt++)
                #pragma unroll
                for (int nt = 0; nt < 4; nt++)
                    mma_bf16(acc[mt][nt][0], acc[mt][nt][1],
                             acc[mt][nt][2], acc[mt][nt][3],
                             afr[kk][mt][0], afr[kk][mt][1], afr[kk][mt][2], afr[kk][mt][3],
                             bfr[kk][nt][0], bfr[kk][nt][1]);
    }

    // epilogue
    #pragma unroll
    for (int mt = 0; mt < 4; mt++) {
        int row0 = rowBase + wm + mt * 16 + g;
        OutT* crow0 = C + (size_t)row0 * Nreal;
        OutT* crow1 = C + (size_t)(row0 + 8) * Nreal;
        #pragma unroll
        for (int nt = 0; nt < 4; nt++) {
            int col0 = colBase + wn + nt * 8 + 2 * t;
            if constexpr (EPI == 0) {
                float b0 = bias[col0], b1 = bias[col0 + 1];
                float v0 = gelu_tanh(acc[mt][nt][0] + b0);
                float v1 = gelu_tanh(acc[mt][nt][1] + b1);
                float v2 = gelu_tanh(acc[mt][nt][2] + b0);
                float v3 = gelu_tanh(acc[mt][nt][3] + b1);
                __nv_bfloat162 p0, p1;
                p0.x = __float2bfloat16_rn(v0); p0.y = __float2bfloat16_rn(v1);
                p1.x = __float2bfloat16_rn(v2); p1.y = __float2bfloat16_rn(v3);
                *(__nv_bfloat162*)&crow0[col0] = p0;
                *(__nv_bfloat162*)&crow1[col0] = p1;
            } else {
                if (col0 + 1 < Nreal) {
                    float b0 = bias[col0], b1 = bias[col0 + 1];
                    float2 p0 = make_float2(acc[mt][nt][0] + b0, acc[mt][nt][1] + b1);
                    float2 p1 = make_float2(acc[mt][nt][2] + b0, acc[mt][nt][3] + b1);
                    *(float2*)&crow0[col0] = p0;
                    *(float2*)&crow1[col0] = p1;
                } else if (col0 < Nreal) {
                    float b0 = bias[col0];
                    crow0[col0] = acc[mt][nt][0] + b0;
                    crow1[col0] = acc[mt][nt][2] + b0;
                }
            }
        }
    }
}

// ---------------------------------------------------------------------------
// per-row softmax * p_gen + shared-memory scatter-add, write out.
// ---------------------------------------------------------------------------
#define SMT 512
__global__ __launch_bounds__(SMT)
void softmax_scatter_kernel(const float* __restrict__ attn,
                            const int*   __restrict__ nodes,
                            const float* __restrict__ pgen,
                            float* __restrict__ out) {
    __shared__ float srow[V_];
    __shared__ float red[17];

    const int r   = blockIdx.x;
    const int b   = r / T_;
    const int tid = threadIdx.x;
    float* orow   = out + (size_t)r * V_;
    const int nwarp = SMT / 32;

    float mx = -3.0e38f;
    for (int i = tid; i < V_ / 4; i += SMT) {
        float4 v = ((const float4*)orow)[i];
        ((float4*)srow)[i] = v;
        mx = fmaxf(fmaxf(mx, fmaxf(v.x, v.y)), fmaxf(v.z, v.w));
    }
    #pragma unroll
    for (int o = 16; o; o >>= 1) mx = fmaxf(mx, __shfl_xor_sync(0xFFFFFFFFu, mx, o));
    if ((tid & 31) == 0) red[tid >> 5] = mx;
    __syncthreads();
    if (tid < nwarp) {
        float v = red[tid];
        #pragma unroll
        for (int o = 8; o; o >>= 1) v = fmaxf(v, __shfl_xor_sync(0xFFFFu, v, o));
        if (tid == 0) red[16] = v;
    }
    __syncthreads();
    mx = red[16];

    float sum = 0.f;
    for (int i = tid; i < V_ / 4; i += SMT) {
        float4 v = ((float4*)srow)[i];
        v.x = __expf(v.x - mx); v.y = __expf(v.y - mx);
        v.z = __expf(v.z - mx); v.w = __expf(v.w - mx);
        ((float4*)srow)[i] = v;
        sum += v.x + v.y + v.z + v.w;
    }
    __syncthreads();
    #pragma unroll
    for (int o = 16; o; o >>= 1) sum += __shfl_xor_sync(0xFFFFFFFFu, sum, o);
    if ((tid & 31) == 0) red[tid >> 5] = sum;
    __syncthreads();
    if (tid < nwarp) {
        float v = red[tid];
        #pragma unroll
        for (int o = 8; o; o >>= 1) v += __shfl_xor_sync(0xFFFFu, v, o);
        if (tid == 0) red[16] = v;
    }
    __syncthreads();
    sum = red[16];

    const float pg    = pgen[r];
    const float scale = pg / sum;
    for (int i = tid; i < V_ / 4; i += SMT) {
        float4 v = ((float4*)srow)[i];
        v.x *= scale; v.y *= scale; v.z *= scale; v.w *= scale;
        ((float4*)srow)[i] = v;
    }
    __syncthreads();

    const float cpg = 1.f - pg;
    const float* ar = attn  + (size_t)r * S_;
    const int*   nb = nodes + (size_t)b * S_;
    for (int i = tid; i < S_ / 4; i += SMT) {
        float4 av = ((const float4*)ar)[i];
        int4   nv = ((const int4*)nb)[i];
        atomicAdd(&srow[nv.x], av.x * cpg);
        atomicAdd(&srow[nv.y], av.y * cpg);
        atomicAdd(&srow[nv.z], av.z * cpg);
        atomicAdd(&srow[nv.w], av.w * cpg);
    }
    __syncthreads();

    for (int i = tid; i < V_ / 4; i += SMT)
        ((float4*)orow)[i] = ((const float4*)srow)[i];
}

// ---------------------------------------------------------------------------
// Launch
// ---------------------------------------------------------------------------
extern "C" void kernel_launch(void* const* d_in, const int* in_sizes, int n_in,
                              void* d_out, int out_size) {
    const float* x    = (const float*)d_in[0];
    const float* attn = (const float*)d_in[1];
    const int*   nodes= (const int*)  d_in[2];
    const float* Wg   = (const float*)d_in[3];
    const float* bg   = (const float*)d_in[4];
    const float* Wf   = (const float*)d_in[5];
    const float* bf   = (const float*)d_in[6];
    const float* Wv   = (const float*)d_in[7];
    const float* bv   = (const float*)d_in[8];
    float* out        = (float*)d_out;

    __nv_bfloat16* xb;   cudaGetSymbolAddress((void**)&xb,   g_xb);
    __nv_bfloat16* hb;   cudaGetSymbolAddress((void**)&hb,   g_hb);
    float* pgen;         cudaGetSymbolAddress((void**)&pgen, g_pgen);
    __nv_bfloat16* WfTb; cudaGetSymbolAddress((void**)&WfTb, g_WfTb);
    __nv_bfloat16* WvTb; cudaGetSymbolAddress((void**)&WvTb, g_WvTb);

    cudaFuncSetAttribute((const void*)bf16_gemm_kernel<0, __nv_bfloat16>,
                         cudaFuncAttributeMaxDynamicSharedMemorySize, DYNSMEM2);
    cudaFuncSetAttribute((const void*)bf16_gemm_kernel<1, float>,
                         cudaFuncAttributeMaxDynamicSharedMemorySize, DYNSMEM2);

    // prep: weight transposes (bf16, K-major)
    transpose_bf16_kernel<<<dim3(H_ / 32, H_ / 32), dim3(32, 8)>>>(Wf, WfTb, H_, H_, H_);
    transpose_bf16_kernel<<<dim3(VPAD / 32, H_ / 32), dim3(32, 8)>>>(Wv, WvTb, H_, V_, VPAD);

    // p_gen (fp32 dot) + x -> bf16 (fused)
    pgen_cvt_kernel<<<M_, 256>>>(x, Wg, bg, pgen, xb);

    // h_bf16 = gelu(x @ Wf + bf)
    bf16_gemm_kernel<0, __nv_bfloat16><<<dim3(H_ / BN, M_ / BM), 256, DYNSMEM2>>>(
        xb, WfTb, bf, hb, H_, H_);

    // logits = h_bf @ Wv + bv -> d_out
    bf16_gemm_kernel<1, float><<<dim3(VPAD / BN, M_ / BM), 256, DYNSMEM2>>>(
        hb, WvTb, bv, out, V_, H_);

    // softmax * p_gen + pointer scatter
    softmax_scatter_kernel<<<M_, SMT>>>(attn, nodes, pgen, out);
}

// round 10
// speedup vs baseline: 5.2259x; 1.0215x over previous
#include <cuda_runtime.h>
#include <cuda_bf16.h>
#include <cstdint>

// Problem constants
#define B_  8
#define T_  1024
#define S_  1024
#define H_  1024
#define V_  5000
#define M_  (B_ * T_)   // 8192 rows
#define VPAD 5120       // V padded to multiple of 128

// Scratch (static device globals — allocation-free)
__device__ __nv_bfloat16 g_xb[(size_t)M_ * H_];    // x in bf16, 16 MB
__device__ __nv_bfloat16 g_hb[(size_t)M_ * H_];    // gelu(x@Wf+bf) in bf16, 16 MB
__device__ float g_pgen[M_];                       // sigmoid(x@Wg + bg)
__device__ __nv_bfloat16 g_WfTb[(size_t)H_ * H_];  // Wf^T bf16 [N=H][K=H]
__device__ __nv_bfloat16 g_WvTb[(size_t)VPAD * H_];// Wv^T bf16 [N=VPAD][K=H], padded

// ---------------------------------------------------------------------------
// helpers
// ---------------------------------------------------------------------------
__device__ __forceinline__ uint32_t smem_u32(const void* p) {
    return (uint32_t)__cvta_generic_to_shared(p);
}
__device__ __forceinline__ void cp_async16(uint32_t dst, const void* src) {
    asm volatile("cp.async.cg.shared.global [%0], [%1], 16;" :: "r"(dst), "l"(src));
}
__device__ __forceinline__ void cp_commit() {
    asm volatile("cp.async.commit_group;" ::: "memory");
}
template <int N>
__device__ __forceinline__ void cp_wait() {
    asm volatile("cp.async.wait_group %0;" :: "n"(N) : "memory");
}

// m16n8k16 bf16 mma (sm_80+)
__device__ __forceinline__ void mma_bf16(float& d0, float& d1, float& d2, float& d3,
                                         uint32_t a0, uint32_t a1, uint32_t a2, uint32_t a3,
                                         uint32_t b0, uint32_t b1) {
    asm volatile(
        "mma.sync.aligned.m16n8k16.row.col.f32.bf16.bf16.f32 "
        "{%0,%1,%2,%3}, {%4,%5,%6,%7}, {%8,%9}, {%0,%1,%2,%3};"
        : "+f"(d0), "+f"(d1), "+f"(d2), "+f"(d3)
        : "r"(a0), "r"(a1), "r"(a2), "r"(a3), "r"(b0), "r"(b1));
}

__device__ __forceinline__ void ldsm_x4(uint32_t& r0, uint32_t& r1, uint32_t& r2, uint32_t& r3,
                                        uint32_t addr) {
    asm volatile("ldmatrix.sync.aligned.m8n8.x4.shared.b16 {%0,%1,%2,%3}, [%4];"
                 : "=r"(r0), "=r"(r1), "=r"(r2), "=r"(r3) : "r"(addr));
}

__device__ __forceinline__ float gelu_tanh(float v) {
    const float c = 0.7978845608028654f;   // sqrt(2/pi)
    float u = c * (v + 0.044715f * v * v * v);
    return 0.5f * v * (1.f + tanhf(u));
}

// ---------------------------------------------------------------------------
// Transpose fp32 -> bf16, 32x32 tiles, zero-pad rows beyond C.
// ---------------------------------------------------------------------------
__global__ void transpose_bf16_kernel(const float* __restrict__ W, __nv_bfloat16* __restrict__ Wt,
                                      int R, int C, int Cpad) {
    __shared__ float t[32][33];
    int c0 = blockIdx.x * 32;
    int r0 = blockIdx.y * 32;
    #pragma unroll
    for (int k = 0; k < 4; k++) {
        int r = r0 + threadIdx.y + k * 8;
        int c = c0 + threadIdx.x;
        float v = 0.f;
        if (r < R && c < C) v = W[(size_t)r * C + c];
        t[threadIdx.y + k * 8][threadIdx.x] = v;
    }
    __syncthreads();
    #pragma unroll
    for (int k = 0; k < 4; k++) {
        int rr = c0 + threadIdx.y + k * 8;
        int cc = r0 + threadIdx.x;
        if (rr < Cpad && cc < R)
            Wt[(size_t)rr * R + cc] = __float2bfloat16_rn(t[threadIdx.x][threadIdx.y + k * 8]);
    }
}

// ---------------------------------------------------------------------------
// Fused: p_gen = sigmoid(x @ Wg + bg)  AND  xb = bf16(x)
// ---------------------------------------------------------------------------
__global__ __launch_bounds__(256)
void pgen_cvt_kernel(const float* __restrict__ x,
                     const float* __restrict__ Wg,
                     const float* __restrict__ bg,
                     float* __restrict__ pgen,
                     __nv_bfloat16* __restrict__ xb) {
    int r = blockIdx.x;
    const float* xr = x + (size_t)r * H_;
    __nv_bfloat16* xbr = xb + (size_t)r * H_;

    float s = 0.f;
    for (int i = threadIdx.x; i < H_ / 4; i += 256) {
        float4 v = ((const float4*)xr)[i];
        float4 w = ((const float4*)Wg)[i];
        s += v.x * w.x + v.y * w.y + v.z * w.z + v.w * w.w;
        __nv_bfloat162 p0, p1;
        p0.x = __float2bfloat16_rn(v.x); p0.y = __float2bfloat16_rn(v.y);
        p1.x = __float2bfloat16_rn(v.z); p1.y = __float2bfloat16_rn(v.w);
        ((__nv_bfloat162*)xbr)[2 * i]     = p0;
        ((__nv_bfloat162*)xbr)[2 * i + 1] = p1;
    }
    __shared__ float red[8];
    #pragma unroll
    for (int o = 16; o; o >>= 1) s += __shfl_xor_sync(0xFFFFFFFFu, s, o);
    if ((threadIdx.x & 31) == 0) red[threadIdx.x >> 5] = s;
    __syncthreads();
    if (threadIdx.x < 8) {
        s = red[threadIdx.x];
        #pragma unroll
        for (int o = 4; o; o >>= 1) s += __shfl_xor_sync(0xFFu, s, o);
        if (threadIdx.x == 0) {
            float z = s + bg[0];
            pgen[r] = 1.f / (1.f + expf(-z));
        }
    }
}

// ---------------------------------------------------------------------------
// Unified bf16 mma.sync GEMM: C = epi(A[M,K] @ Bt[N,K]^T + bias[N])
// BM=BN=128, BK=32 bf16, 256 threads (8 warps 2x4), warp tile 64x32.
// 5-stage cp.async ring, ONE cp_wait + ONE __syncthreads per TWO iterations;
// the two stages' LDSM/MMA streams overlap freely between barriers.
// SMEM rows padded to 40 bf16 -> conflict-free LDSM.
// EPI 0: gelu -> bf16 out.  EPI 1: identity -> fp32 out (ragged N).
// ---------------------------------------------------------------------------
#define BM 128
#define BN 128
#define BK 32
#define KP2 40
#define STAGE2_BYTES (128 * KP2 * 2)          // 10240 B per operand per stage
#define NSTAGE 5
#define DYNSMEM2 (NSTAGE * 2 * STAGE2_BYTES)  // 102400 B (2 CTAs = 204.8 KB/SM)

template <int EPI, typename OutT>
__global__ __launch_bounds__(256, 2)
void bf16_gemm_kernel(const __nv_bfloat16* __restrict__ A,
                      const __nv_bfloat16* __restrict__ Bt,
                      const float* __restrict__ bias, OutT* __restrict__ C,
                      int Nreal, int K) {
    extern __shared__ char sm2[];
    uint32_t base = smem_u32(sm2);
    uint32_t AsO[NSTAGE], BsO[NSTAGE];
    #pragma unroll
    for (int s = 0; s < NSTAGE; s++) {
        AsO[s] = base + (uint32_t)s * 2 * STAGE2_BYTES;
        BsO[s] = AsO[s] + STAGE2_BYTES;
    }

    const int tid  = threadIdx.x;
    const int wid  = tid >> 5;
    const int lane = tid & 31;
    const int g    = lane >> 2;
    const int t    = lane & 3;
    const int wm   = (wid >> 2) * 64;
    const int wn   = (wid & 3) * 32;

    const int rowBase = blockIdx.y * BM;
    const int colBase = blockIdx.x * BN;
    const int NK = K / BK;               // 32 (even)

    const __nv_bfloat16* Abase = A  + (size_t)rowBase * K;
    const __nv_bfloat16* Bbase = Bt + (size_t)colBase * K;

    float acc[4][4][4];
    #pragma unroll
    for (int i = 0; i < 4; i++)
        #pragma unroll
        for (int j = 0; j < 4; j++)
            #pragma unroll
            for (int r = 0; r < 4; r++) acc[i][j][r] = 0.f;

    auto load_stage = [&](int st, int k0) {
        #pragma unroll
        for (int i = 0; i < 2; i++) {
            int idx = tid + i * 256;        // 0..511
            int r   = idx >> 2;             // 0..127
            int c   = idx & 3;              // 16B chunk
            uint32_t off = (uint32_t)(r * (KP2 * 2) + c * 16);
            cp_async16(AsO[st] + off, Abase + (size_t)r * K + k0 + c * 8);
            cp_async16(BsO[st] + off, Bbase + (size_t)r * K + k0 + c * 8);
        }
        cp_commit();
    };

    // ldmatrix per-thread address components
    const uint32_t aRowOff = (uint32_t)(lane & 15) * (KP2 * 2);
    const uint32_t aKh     = (uint32_t)(lane >> 4) * 16;
    const uint32_t bRowOff = (uint32_t)((lane & 7) + ((lane >> 4) << 3)) * (KP2 * 2);
    const uint32_t bKh     = (uint32_t)((lane >> 3) & 1) * 16;

    // compute one stage: 12 LDSM then 32 MMA
    auto compute_stage = [&](int st) {
        uint32_t as = AsO[st];
        uint32_t bs = BsO[st];
        uint32_t afr[2][4][4];
        uint32_t bfr[2][4][2];
        #pragma unroll
        for (int kk = 0; kk < 2; kk++) {
            uint32_t kb = kk * 32;
            #pragma unroll
            for (int mt = 0; mt < 4; mt++)
                ldsm_x4(afr[kk][mt][0], afr[kk][mt][1], afr[kk][mt][2], afr[kk][mt][3],
                        as + (uint32_t)(wm + mt * 16) * (KP2 * 2) + aRowOff + kb + aKh);
            #pragma unroll
            for (int p = 0; p < 2; p++) {
                uint32_t r0, r1, r2, r3;
                ldsm_x4(r0, r1, r2, r3,
                        bs + (uint32_t)(wn + p * 16) * (KP2 * 2) + bRowOff + kb + bKh);
                bfr[kk][2 * p][0]     = r0; bfr[kk][2 * p][1]     = r1;
                bfr[kk][2 * p + 1][0] = r2; bfr[kk][2 * p + 1][1] = r3;
            }
        }
        #pragma unroll
        for (int kk = 0; kk < 2; kk++)
            #pragma unroll
            for (int mt = 0; mt < 4; mt++)
                #pragma unroll
                for (int nt = 0; nt < 4; nt++)
                    mma_bf16(acc[mt][nt][0], acc[mt][nt][1],
                             acc[mt][nt][2], acc[mt][nt][3],
                             afr[kk][mt][0], afr[kk][mt][1], afr[kk][mt][2], afr[kk][mt][3],
                             bfr[kk][nt][0], bfr[kk][nt][1]);
    };

    // prologue: stages 0,1,2  (3 groups in flight)
    load_stage(0, 0);
    load_stage(1, BK);
    load_stage(2, 2 * BK);

    // steady state: one wait+sync per TWO iterations
    for (int j = 0; j < NK; j += 2) {
        if (j + 2 < NK) { cp_wait<1>(); }   // stages j, j+1 complete; j+2 may fly
        else            { cp_wait<0>(); }
        __syncthreads();   // also guarantees slots (j+3)%5, (j+4)%5 are free

        if (j + 3 < NK) load_stage((j + 3) % NSTAGE, (j + 3) * BK);
        if (j + 4 < NK) load_stage((j + 4) % NSTAGE, (j + 4) * BK);

        compute_stage(j % NSTAGE);
        compute_stage((j + 1) % NSTAGE);
    }

    // epilogue
    #pragma unroll
    for (int mt = 0; mt < 4; mt++) {
        int row0 = rowBase + wm + mt * 16 + g;
        OutT* crow0 = C + (size_t)row0 * Nreal;
        OutT* crow1 = C + (size_t)(row0 + 8) * Nreal;
        #pragma unroll
        for (int nt = 0; nt < 4; nt++) {
            int col0 = colBase + wn + nt * 8 + 2 * t;
            if constexpr (EPI == 0) {
                float b0 = bias[col0], b1 = bias[col0 + 1];
                float v0 = gelu_tanh(acc[mt][nt][0] + b0);
                float v1 = gelu_tanh(acc[mt][nt][1] + b1);
                float v2 = gelu_tanh(acc[mt][nt][2] + b0);
                float v3 = gelu_tanh(acc[mt][nt][3] + b1);
                __nv_bfloat162 p0, p1;
                p0.x = __float2bfloat16_rn(v0); p0.y = __float2bfloat16_rn(v1);
                p1.x = __float2bfloat16_rn(v2); p1.y = __float2bfloat16_rn(v3);
                *(__nv_bfloat162*)&crow0[col0] = p0;
                *(__nv_bfloat162*)&crow1[col0] = p1;
            } else {
                if (col0 + 1 < Nreal) {
                    float b0 = bias[col0], b1 = bias[col0 + 1];
                    float2 p0 = make_float2(acc[mt][nt][0] + b0, acc[mt][nt][1] + b1);
                    float2 p1 = make_float2(acc[mt][nt][2] + b0, acc[mt][nt][3] + b1);
                    *(float2*)&crow0[col0] = p0;
                    *(float2*)&crow1[col0] = p1;
                } else if (col0 < Nreal) {
                    float b0 = bias[col0];
                    crow0[col0] = acc[mt][nt][0] + b0;
                    crow1[col0] = acc[mt][nt][2] + b0;
                }
            }
        }
    }
}

// ---------------------------------------------------------------------------
// per-row softmax * p_gen + shared-memory scatter-add, write out.
// ---------------------------------------------------------------------------
#define SMT 512
__global__ __launch_bounds__(SMT)
void softmax_scatter_kernel(const float* __restrict__ attn,
                            const int*   __restrict__ nodes,
                            const float* __restrict__ pgen,
                            float* __restrict__ out) {
    __shared__ float srow[V_];
    __shared__ float red[17];

    const int r   = blockIdx.x;
    const int b   = r / T_;
    const int tid = threadIdx.x;
    float* orow   = out + (size_t)r * V_;
    const int nwarp = SMT / 32;

    float mx = -3.0e38f;
    for (int i = tid; i < V_ / 4; i += SMT) {
        float4 v = ((const float4*)orow)[i];
        ((float4*)srow)[i] = v;
        mx = fmaxf(fmaxf(mx, fmaxf(v.x, v.y)), fmaxf(v.z, v.w));
    }
    #pragma unroll
    for (int o = 16; o; o >>= 1) mx = fmaxf(mx, __shfl_xor_sync(0xFFFFFFFFu, mx, o));
    if ((tid & 31) == 0) red[tid >> 5] = mx;
    __syncthreads();
    if (tid < nwarp) {
        float v = red[tid];
        #pragma unroll
        for (int o = 8; o; o >>= 1) v = fmaxf(v, __shfl_xor_sync(0xFFFFu, v, o));
        if (tid == 0) red[16] = v;
    }
    __syncthreads();
    mx = red[16];

    float sum = 0.f;
    for (int i = tid; i < V_ / 4; i += SMT) {
        float4 v = ((float4*)srow)[i];
        v.x = __expf(v.x - mx); v.y = __expf(v.y - mx);
        v.z = __expf(v.z - mx); v.w = __expf(v.w - mx);
        ((float4*)srow)[i] = v;
        sum += v.x + v.y + v.z + v.w;
    }
    __syncthreads();
    #pragma unroll
    for (int o = 16; o; o >>= 1) sum += __shfl_xor_sync(0xFFFFFFFFu, sum, o);
    if ((tid & 31) == 0) red[tid >> 5] = sum;
    __syncthreads();
    if (tid < nwarp) {
        float v = red[tid];
        #pragma unroll
        for (int o = 8; o; o >>= 1) v += __shfl_xor_sync(0xFFFFu, v, o);
        if (tid == 0) red[16] = v;
    }
    __syncthreads();
    sum = red[16];

    const float pg    = pgen[r];
    const float scale = pg / sum;
    for (int i = tid; i < V_ / 4; i += SMT) {
        float4 v = ((float4*)srow)[i];
        v.x *= scale; v.y *= scale; v.z *= scale; v.w *= scale;
        ((float4*)srow)[i] = v;
    }
    __syncthreads();

    const float cpg = 1.f - pg;
    const float* ar = attn  + (size_t)r * S_;
    const int*   nb = nodes + (size_t)b * S_;
    for (int i = tid; i < S_ / 4; i += SMT) {
        float4 av = ((const float4*)ar)[i];
        int4   nv = ((const int4*)nb)[i];
        atomicAdd(&srow[nv.x], av.x * cpg);
        atomicAdd(&srow[nv.y], av.y * cpg);
        atomicAdd(&srow[nv.z], av.z * cpg);
        atomicAdd(&srow[nv.w], av.w * cpg);
    }
    __syncthreads();

    for (int i = tid; i < V_ / 4; i += SMT)
        ((float4*)orow)[i] = ((const float4*)srow)[i];
}

// ---------------------------------------------------------------------------
// Launch
// ---------------------------------------------------------------------------
extern "C" void kernel_launch(void* const* d_in, const int* in_sizes, int n_in,
                              void* d_out, int out_size) {
    const float* x    = (const float*)d_in[0];
    const float* attn = (const float*)d_in[1];
    const int*   nodes= (const int*)  d_in[2];
    const float* Wg   = (const float*)d_in[3];
    const float* bg   = (const float*)d_in[4];
    const float* Wf   = (const float*)d_in[5];
    const float* bf   = (const float*)d_in[6];
    const float* Wv   = (const float*)d_in[7];
    const float* bv   = (const float*)d_in[8];
    float* out        = (float*)d_out;

    __nv_bfloat16* xb;   cudaGetSymbolAddress((void**)&xb,   g_xb);
    __nv_bfloat16* hb;   cudaGetSymbolAddress((void**)&hb,   g_hb);
    float* pgen;         cudaGetSymbolAddress((void**)&pgen, g_pgen);
    __nv_bfloat16* WfTb; cudaGetSymbolAddress((void**)&WfTb, g_WfTb);
    __nv_bfloat16* WvTb; cudaGetSymbolAddress((void**)&WvTb, g_WvTb);

    cudaFuncSetAttribute((const void*)bf16_gemm_kernel<0, __nv_bfloat16>,
                         cudaFuncAttributeMaxDynamicSharedMemorySize, DYNSMEM2);
    cudaFuncSetAttribute((const void*)bf16_gemm_kernel<1, float>,
                         cudaFuncAttributeMaxDynamicSharedMemorySize, DYNSMEM2);

    // prep: weight transposes (bf16, K-major)
    transpose_bf16_kernel<<<dim3(H_ / 32, H_ / 32), dim3(32, 8)>>>(Wf, WfTb, H_, H_, H_);
    transpose_bf16_kernel<<<dim3(VPAD / 32, H_ / 32), dim3(32, 8)>>>(Wv, WvTb, H_, V_, VPAD);

    // p_gen (fp32 dot) + x -> bf16 (fused)
    pgen_cvt_kernel<<<M_, 256>>>(x, Wg, bg, pgen, xb);

    // h_bf16 = gelu(x @ Wf + bf)
    bf16_gemm_kernel<0, __nv_bfloat16><<<dim3(H_ / BN, M_ / BM), 256, DYNSMEM2>>>(
        xb, WfTb, bf, hb, H_, H_);

    // logits = h_bf @ Wv + bv -> d_out
    bf16_gemm_kernel<1, float><<<dim3(VPAD / BN, M_ / BM), 256, DYNSMEM2>>>(
        hb, WvTb, bv, out, V_, H_);

    // softmax * p_gen + pointer scatter
    softmax_scatter_kernel<<<M_, SMT>>>(attn, nodes, pgen, out);
}

// round 11
// speedup vs baseline: 5.3169x; 1.0174x over previous
#include <cuda_runtime.h>
#include <cuda_bf16.h>
#include <cstdint>

// Problem constants
#define B_  8
#define T_  1024
#define S_  1024
#define H_  1024
#define V_  5000
#define M_  (B_ * T_)   // 8192 rows
#define VPAD 5120       // V padded to multiple of 128

// Scratch (static device globals — allocation-free)
__device__ __nv_bfloat16 g_xb[(size_t)M_ * H_];    // x in bf16, 16 MB
__device__ __nv_bfloat16 g_hb[(size_t)M_ * H_];    // gelu(x@Wf+bf) in bf16, 16 MB
__device__ float g_pgen[M_];                       // sigmoid(x@Wg + bg)
__device__ __nv_bfloat16 g_WfTb[(size_t)H_ * H_];  // Wf^T bf16 [N=H][K=H]
__device__ __nv_bfloat16 g_WvTb[(size_t)VPAD * H_];// Wv^T bf16 [N=VPAD][K=H], padded

// ---------------------------------------------------------------------------
// helpers
// ---------------------------------------------------------------------------
__device__ __forceinline__ uint32_t smem_u32(const void* p) {
    return (uint32_t)__cvta_generic_to_shared(p);
}
__device__ __forceinline__ void cp_async16(uint32_t dst, const void* src) {
    asm volatile("cp.async.cg.shared.global [%0], [%1], 16;" :: "r"(dst), "l"(src));
}
__device__ __forceinline__ void cp_commit() {
    asm volatile("cp.async.commit_group;" ::: "memory");
}
template <int N>
__device__ __forceinline__ void cp_wait() {
    asm volatile("cp.async.wait_group %0;" :: "n"(N) : "memory");
}

// m16n8k16 bf16 mma (sm_80+)
__device__ __forceinline__ void mma_bf16(float& d0, float& d1, float& d2, float& d3,
                                         uint32_t a0, uint32_t a1, uint32_t a2, uint32_t a3,
                                         uint32_t b0, uint32_t b1) {
    asm volatile(
        "mma.sync.aligned.m16n8k16.row.col.f32.bf16.bf16.f32 "
        "{%0,%1,%2,%3}, {%4,%5,%6,%7}, {%8,%9}, {%0,%1,%2,%3};"
        : "+f"(d0), "+f"(d1), "+f"(d2), "+f"(d3)
        : "r"(a0), "r"(a1), "r"(a2), "r"(a3), "r"(b0), "r"(b1));
}

__device__ __forceinline__ void ldsm_x4(uint32_t& r0, uint32_t& r1, uint32_t& r2, uint32_t& r3,
                                        uint32_t addr) {
    asm volatile("ldmatrix.sync.aligned.m8n8.x4.shared.b16 {%0,%1,%2,%3}, [%4];"
                 : "=r"(r0), "=r"(r1), "=r"(r2), "=r"(r3) : "r"(addr));
}

__device__ __forceinline__ float gelu_tanh(float v) {
    const float c = 0.7978845608028654f;   // sqrt(2/pi)
    float u = c * (v + 0.044715f * v * v * v);
    return 0.5f * v * (1.f + tanhf(u));
}

// ---------------------------------------------------------------------------
// Transpose fp32 -> bf16, 32x32 tiles, zero-pad rows beyond C.
// ---------------------------------------------------------------------------
__global__ void transpose_bf16_kernel(const float* __restrict__ W, __nv_bfloat16* __restrict__ Wt,
                                      int R, int C, int Cpad) {
    __shared__ float t[32][33];
    int c0 = blockIdx.x * 32;
    int r0 = blockIdx.y * 32;
    #pragma unroll
    for (int k = 0; k < 4; k++) {
        int r = r0 + threadIdx.y + k * 8;
        int c = c0 + threadIdx.x;
        float v = 0.f;
        if (r < R && c < C) v = W[(size_t)r * C + c];
        t[threadIdx.y + k * 8][threadIdx.x] = v;
    }
    __syncthreads();
    #pragma unroll
    for (int k = 0; k < 4; k++) {
        int rr = c0 + threadIdx.y + k * 8;
        int cc = r0 + threadIdx.x;
        if (rr < Cpad && cc < R)
            Wt[(size_t)rr * R + cc] = __float2bfloat16_rn(t[threadIdx.x][threadIdx.y + k * 8]);
    }
}

// ---------------------------------------------------------------------------
// Fused: p_gen = sigmoid(x @ Wg + bg)  AND  xb = bf16(x)
// ---------------------------------------------------------------------------
__global__ __launch_bounds__(256)
void pgen_cvt_kernel(const float* __restrict__ x,
                     const float* __restrict__ Wg,
                     const float* __restrict__ bg,
                     float* __restrict__ pgen,
                     __nv_bfloat16* __restrict__ xb) {
    int r = blockIdx.x;
    const float* xr = x + (size_t)r * H_;
    __nv_bfloat16* xbr = xb + (size_t)r * H_;

    float s = 0.f;
    for (int i = threadIdx.x; i < H_ / 4; i += 256) {
        float4 v = ((const float4*)xr)[i];
        float4 w = ((const float4*)Wg)[i];
        s += v.x * w.x + v.y * w.y + v.z * w.z + v.w * w.w;
        __nv_bfloat162 p0, p1;
        p0.x = __float2bfloat16_rn(v.x); p0.y = __float2bfloat16_rn(v.y);
        p1.x = __float2bfloat16_rn(v.z); p1.y = __float2bfloat16_rn(v.w);
        ((__nv_bfloat162*)xbr)[2 * i]     = p0;
        ((__nv_bfloat162*)xbr)[2 * i + 1] = p1;
    }
    __shared__ float red[8];
    #pragma unroll
    for (int o = 16; o; o >>= 1) s += __shfl_xor_sync(0xFFFFFFFFu, s, o);
    if ((threadIdx.x & 31) == 0) red[threadIdx.x >> 5] = s;
    __syncthreads();
    if (threadIdx.x < 8) {
        s = red[threadIdx.x];
        #pragma unroll
        for (int o = 4; o; o >>= 1) s += __shfl_xor_sync(0xFFu, s, o);
        if (threadIdx.x == 0) {
            float z = s + bg[0];
            pgen[r] = 1.f / (1.f + expf(-z));
        }
    }
}

// ---------------------------------------------------------------------------
// Unified bf16 mma.sync GEMM: C = epi(A[M,K] @ Bt[N,K]^T + bias[N])
// BM=BN=128, BK=32 bf16, 256 threads (8 warps 2x4), warp tile 64x32.
// 5-stage cp.async ring, one wait+sync per TWO k-iterations.
// k16-granular SOFTWARE PIPELINE: two fragment register sets ping-pong so
// LDSM of step s+1 issues before the MMAs of step s (crossbar || tensor).
// SMEM rows padded to 40 bf16 -> conflict-free LDSM.
// EPI 0: gelu -> bf16 out.  EPI 1: identity -> fp32 out (ragged N).
// ---------------------------------------------------------------------------
#define BM 128
#define BN 128
#define BK 32
#define KP2 40
#define STAGE2_BYTES (128 * KP2 * 2)          // 10240 B per operand per stage
#define NSTAGE 5
#define DYNSMEM2 (NSTAGE * 2 * STAGE2_BYTES)  // 102400 B (2 CTAs = 204.8 KB/SM)

template <int EPI, typename OutT>
__global__ __launch_bounds__(256, 2)
void bf16_gemm_kernel(const __nv_bfloat16* __restrict__ A,
                      const __nv_bfloat16* __restrict__ Bt,
                      const float* __restrict__ bias, OutT* __restrict__ C,
                      int Nreal, int K) {
    extern __shared__ char sm2[];
    uint32_t base = smem_u32(sm2);
    uint32_t AsO[NSTAGE], BsO[NSTAGE];
    #pragma unroll
    for (int s = 0; s < NSTAGE; s++) {
        AsO[s] = base + (uint32_t)s * 2 * STAGE2_BYTES;
        BsO[s] = AsO[s] + STAGE2_BYTES;
    }

    const int tid  = threadIdx.x;
    const int wid  = tid >> 5;
    const int lane = tid & 31;
    const int g    = lane >> 2;
    const int t    = lane & 3;
    const int wm   = (wid >> 2) * 64;
    const int wn   = (wid & 3) * 32;

    const int rowBase = blockIdx.y * BM;
    const int colBase = blockIdx.x * BN;
    const int NK = K / BK;               // 32 (even)

    const __nv_bfloat16* Abase = A  + (size_t)rowBase * K;
    const __nv_bfloat16* Bbase = Bt + (size_t)colBase * K;

    float acc[4][4][4];
    #pragma unroll
    for (int i = 0; i < 4; i++)
        #pragma unroll
        for (int j = 0; j < 4; j++)
            #pragma unroll
            for (int r = 0; r < 4; r++) acc[i][j][r] = 0.f;

    auto load_stage = [&](int st, int k0) {
        #pragma unroll
        for (int i = 0; i < 2; i++) {
            int idx = tid + i * 256;        // 0..511
            int r   = idx >> 2;             // 0..127
            int c   = idx & 3;              // 16B chunk
            uint32_t off = (uint32_t)(r * (KP2 * 2) + c * 16);
            cp_async16(AsO[st] + off, Abase + (size_t)r * K + k0 + c * 8);
            cp_async16(BsO[st] + off, Bbase + (size_t)r * K + k0 + c * 8);
        }
        cp_commit();
    };

    // ldmatrix per-thread address components
    const uint32_t aRowOff = (uint32_t)(lane & 15) * (KP2 * 2);
    const uint32_t aKh     = (uint32_t)(lane >> 4) * 16;
    const uint32_t bRowOff = (uint32_t)((lane & 7) + ((lane >> 4) << 3)) * (KP2 * 2);
    const uint32_t bKh     = (uint32_t)((lane >> 3) & 1) * 16;

    // two fragment register sets (ping-pong)
    uint32_t afr0[4][4], bfr0[4][2];
    uint32_t afr1[4][4], bfr1[4][2];

    // load fragments for one k16-step into the given set
    auto load_frags = [&](uint32_t (&fa)[4][4], uint32_t (&fb)[4][2],
                          uint32_t as, uint32_t bs, uint32_t kb) {
        #pragma unroll
        for (int mt = 0; mt < 4; mt++)
            ldsm_x4(fa[mt][0], fa[mt][1], fa[mt][2], fa[mt][3],
                    as + (uint32_t)(wm + mt * 16) * (KP2 * 2) + aRowOff + kb + aKh);
        #pragma unroll
        for (int p = 0; p < 2; p++) {
            uint32_t r0, r1, r2, r3;
            ldsm_x4(r0, r1, r2, r3,
                    bs + (uint32_t)(wn + p * 16) * (KP2 * 2) + bRowOff + kb + bKh);
            fb[2 * p][0]     = r0; fb[2 * p][1]     = r1;
            fb[2 * p + 1][0] = r2; fb[2 * p + 1][1] = r3;
        }
    };
    // 16 MMAs from one set
    auto mma_all = [&](uint32_t (&fa)[4][4], uint32_t (&fb)[4][2]) {
        #pragma unroll
        for (int mt = 0; mt < 4; mt++)
            #pragma unroll
            for (int nt = 0; nt < 4; nt++)
                mma_bf16(acc[mt][nt][0], acc[mt][nt][1],
                         acc[mt][nt][2], acc[mt][nt][3],
                         fa[mt][0], fa[mt][1], fa[mt][2], fa[mt][3],
                         fb[nt][0], fb[nt][1]);
    };

    // prologue: stages 0,1,2  (3 groups in flight)
    load_stage(0, 0);
    load_stage(1, BK);
    load_stage(2, 2 * BK);

    // steady state: one wait+sync per TWO iterations; k16-pipelined inside
    for (int j = 0; j < NK; j += 2) {
        if (j + 2 < NK) { cp_wait<1>(); }   // stages j, j+1 complete; j+2 may fly
        else            { cp_wait<0>(); }
        __syncthreads();   // also guarantees slots (j+3)%5, (j+4)%5 are free

        if (j + 3 < NK) load_stage((j + 3) % NSTAGE, (j + 3) * BK);
        if (j + 4 < NK) load_stage((j + 4) % NSTAGE, (j + 4) * BK);

        uint32_t asJ  = AsO[j % NSTAGE],       bsJ  = BsO[j % NSTAGE];
        uint32_t asJ1 = AsO[(j + 1) % NSTAGE], bsJ1 = BsO[(j + 1) % NSTAGE];

        // 4 k16-steps, pipelined: LDSM(s+1) issued before MMA(s)
        load_frags(afr0, bfr0, asJ,  bsJ,  0);    // step 0
        load_frags(afr1, bfr1, asJ,  bsJ,  32);   // step 1
        mma_all(afr0, bfr0);                      // mma step 0
        load_frags(afr0, bfr0, asJ1, bsJ1, 0);    // step 2
        mma_all(afr1, bfr1);                      // mma step 1
        load_frags(afr1, bfr1, asJ1, bsJ1, 32);   // step 3
        mma_all(afr0, bfr0);                      // mma step 2
        mma_all(afr1, bfr1);                      // mma step 3
    }

    // epilogue
    #pragma unroll
    for (int mt = 0; mt < 4; mt++) {
        int row0 = rowBase + wm + mt * 16 + g;
        OutT* crow0 = C + (size_t)row0 * Nreal;
        OutT* crow1 = C + (size_t)(row0 + 8) * Nreal;
        #pragma unroll
        for (int nt = 0; nt < 4; nt++) {
            int col0 = colBase + wn + nt * 8 + 2 * t;
            if constexpr (EPI == 0) {
                float b0 = bias[col0], b1 = bias[col0 + 1];
                float v0 = gelu_tanh(acc[mt][nt][0] + b0);
                float v1 = gelu_tanh(acc[mt][nt][1] + b1);
                float v2 = gelu_tanh(acc[mt][nt][2] + b0);
                float v3 = gelu_tanh(acc[mt][nt][3] + b1);
                __nv_bfloat162 p0, p1;
                p0.x = __float2bfloat16_rn(v0); p0.y = __float2bfloat16_rn(v1);
                p1.x = __float2bfloat16_rn(v2); p1.y = __float2bfloat16_rn(v3);
                *(__nv_bfloat162*)&crow0[col0] = p0;
                *(__nv_bfloat162*)&crow1[col0] = p1;
            } else {
                if (col0 + 1 < Nreal) {
                    float b0 = bias[col0], b1 = bias[col0 + 1];
                    float2 p0 = make_float2(acc[mt][nt][0] + b0, acc[mt][nt][1] + b1);
                    float2 p1 = make_float2(acc[mt][nt][2] + b0, acc[mt][nt][3] + b1);
                    *(float2*)&crow0[col0] = p0;
                    *(float2*)&crow1[col0] = p1;
                } else if (col0 < Nreal) {
                    float b0 = bias[col0];
                    crow0[col0] = acc[mt][nt][0] + b0;
                    crow1[col0] = acc[mt][nt][2] + b0;
                }
            }
        }
    }
}

// ---------------------------------------------------------------------------
// per-row softmax * p_gen + shared-memory scatter-add, write out.
// scale folded into write-back; scatter adds pre-divided mass.
// ---------------------------------------------------------------------------
#define SMT 512
__global__ __launch_bounds__(SMT)
void softmax_scatter_kernel(const float* __restrict__ attn,
                            const int*   __restrict__ nodes,
                            const float* __restrict__ pgen,
                            float* __restrict__ out) {
    __shared__ float srow[V_];
    __shared__ float red[17];

    const int r   = blockIdx.x;
    const int b   = r / T_;
    const int tid = threadIdx.x;
    float* orow   = out + (size_t)r * V_;
    const int nwarp = SMT / 32;

    float mx = -3.0e38f;
    for (int i = tid; i < V_ / 4; i += SMT) {
        float4 v = ((const float4*)orow)[i];
        ((float4*)srow)[i] = v;
        mx = fmaxf(fmaxf(mx, fmaxf(v.x, v.y)), fmaxf(v.z, v.w));
    }
    #pragma unroll
    for (int o = 16; o; o >>= 1) mx = fmaxf(mx, __shfl_xor_sync(0xFFFFFFFFu, mx, o));
    if ((tid & 31) == 0) red[tid >> 5] = mx;
    __syncthreads();
    if (tid < nwarp) {
        float v = red[tid];
        #pragma unroll
        for (int o = 8; o; o >>= 1) v = fmaxf(v, __shfl_xor_sync(0xFFFFu, v, o));
        if (tid == 0) red[16] = v;
    }
    __syncthreads();
    mx = red[16];

    float sum = 0.f;
    for (int i = tid; i < V_ / 4; i += SMT) {
        float4 v = ((float4*)srow)[i];
        v.x = __expf(v.x - mx); v.y = __expf(v.y - mx);
        v.z = __expf(v.z - mx); v.w = __expf(v.w - mx);
        ((float4*)srow)[i] = v;
        sum += v.x + v.y + v.z + v.w;
    }
    __syncthreads();
    #pragma unroll
    for (int o = 16; o; o >>= 1) sum += __shfl_xor_sync(0xFFFFFFFFu, sum, o);
    if ((tid & 31) == 0) red[tid >> 5] = sum;
    __syncthreads();
    if (tid < nwarp) {
        float v = red[tid];
        #pragma unroll
        for (int o = 8; o; o >>= 1) v += __shfl_xor_sync(0xFFFFu, v, o);
        if (tid == 0) red[16] = v;
    }
    __syncthreads();
    sum = red[16];

    const float pg    = pgen[r];
    const float scale = pg / sum;                 // final multiplier
    const float caddf = (1.f - pg) * sum / pg;    // pre-divided pointer mass

    // scatter-add pointer mass (pre-divided so one final scale applies)
    const float* ar = attn  + (size_t)r * S_;
    const int*   nb = nodes + (size_t)b * S_;
    for (int i = tid; i < S_ / 4; i += SMT) {
        float4 av = ((const float4*)ar)[i];
        int4   nv = ((const int4*)nb)[i];
        atomicAdd(&srow[nv.x], av.x * caddf);
        atomicAdd(&srow[nv.y], av.y * caddf);
        atomicAdd(&srow[nv.z], av.z * caddf);
        atomicAdd(&srow[nv.w], av.w * caddf);
    }
    __syncthreads();

    // write back with the single scale
    for (int i = tid; i < V_ / 4; i += SMT) {
        float4 v = ((const float4*)srow)[i];
        v.x *= scale; v.y *= scale; v.z *= scale; v.w *= scale;
        ((float4*)orow)[i] = v;
    }
}

// ---------------------------------------------------------------------------
// Launch
// ---------------------------------------------------------------------------
extern "C" void kernel_launch(void* const* d_in, const int* in_sizes, int n_in,
                              void* d_out, int out_size) {
    const float* x    = (const float*)d_in[0];
    const float* attn = (const float*)d_in[1];
    const int*   nodes= (const int*)  d_in[2];
    const float* Wg   = (const float*)d_in[3];
    const float* bg   = (const float*)d_in[4];
    const float* Wf   = (const float*)d_in[5];
    const float* bf   = (const float*)d_in[6];
    const float* Wv   = (const float*)d_in[7];
    const float* bv   = (const float*)d_in[8];
    float* out        = (float*)d_out;

    __nv_bfloat16* xb;   cudaGetSymbolAddress((void**)&xb,   g_xb);
    __nv_bfloat16* hb;   cudaGetSymbolAddress((void**)&hb,   g_hb);
    float* pgen;         cudaGetSymbolAddress((void**)&pgen, g_pgen);
    __nv_bfloat16* WfTb; cudaGetSymbolAddress((void**)&WfTb, g_WfTb);
    __nv_bfloat16* WvTb; cudaGetSymbolAddress((void**)&WvTb, g_WvTb);

    cudaFuncSetAttribute((const void*)bf16_gemm_kernel<0, __nv_bfloat16>,
                         cudaFuncAttributeMaxDynamicSharedMemorySize, DYNSMEM2);
    cudaFuncSetAttribute((const void*)bf16_gemm_kernel<1, float>,
                         cudaFuncAttributeMaxDynamicSharedMemorySize, DYNSMEM2);

    // prep: weight transposes (bf16, K-major)
    transpose_bf16_kernel<<<dim3(H_ / 32, H_ / 32), dim3(32, 8)>>>(Wf, WfTb, H_, H_, H_);
    transpose_bf16_kernel<<<dim3(VPAD / 32, H_ / 32), dim3(32, 8)>>>(Wv, WvTb, H_, V_, VPAD);

    // p_gen (fp32 dot) + x -> bf16 (fused)
    pgen_cvt_kernel<<<M_, 256>>>(x, Wg, bg, pgen, xb);

    // h_bf16 = gelu(x @ Wf + bf)
    bf16_gemm_kernel<0, __nv_bfloat16><<<dim3(H_ / BN, M_ / BM), 256, DYNSMEM2>>>(
        xb, WfTb, bf, hb, H_, H_);

    // logits = h_bf @ Wv + bv -> d_out
    bf16_gemm_kernel<1, float><<<dim3(VPAD / BN, M_ / BM), 256, DYNSMEM2>>>(
        hb, WvTb, bv, out, V_, H_);

    // softmax * p_gen + pointer scatter
    softmax_scatter_kernel<<<M_, SMT>>>(attn, nodes, pgen, out);
}